// round 11
// baseline (speedup 1.0000x reference)
#include <cuda_runtime.h>
#include <cuda_bf16.h>
#include <cstdint>

#define DD 128
#define NODES_MAX 50000
#define NE_MAX 640000
#define NGRAPH 64
#define NCLASS 32
#define BM 128
#define TILES_PER_CTA 2

// ---- smem layout for mma MLP (bytes from dynamic smem base) ----
#define SAB   272                    // bytes per bf16 row (136 elems) -> conflict-free ldmatrix
#define MATB  (128 * SAB)            // 34816 bytes per 128x128 bf16 matrix
#define SM_B1 0
#define SM_B2 512
#define SM_AH 1024
#define SM_AL (SM_AH + MATB)
#define SM_W  (SM_AL + MATB)         // [W1hi|W1lo|W2hi|W2lo]
#define MLP_SMEM (SM_W + 4 * MATB)   // 209920 bytes

#define WL_BYTES (4 * MATB)          // per-layer prepped weights

__device__ float g_bufA[NODES_MAX * DD];
__device__ float g_bufB[NODES_MAX * DD];
__device__ float g_pool[NGRAPH * DD];
__device__ float g_cnt[NGRAPH];
__device__ float g_scratch[NGRAPH * DD + NGRAPH * NCLASS];
__device__ int   g_is64;
__device__ int   g_deg[NODES_MAX];
__device__ int   g_off[NODES_MAX + 1];
__device__ int   g_cur[NODES_MAX];
__device__ int   g_esrc[NE_MAX];
__device__ int   g_blk[256];
__device__ __align__(16) unsigned char g_wprep[4 * WL_BYTES];

// ================= helpers =================
__device__ __forceinline__ void red_add_v2(float* p, float x, float y) {
    asm volatile("red.global.add.v2.f32 [%0], {%1, %2};"
                 :: "l"(p), "f"(x), "f"(y) : "memory");
}
__device__ __forceinline__ uint32_t smem_u32(const void* p) {
    uint32_t a;
    asm("{ .reg .u64 t; cvta.to.shared.u64 t, %1; cvt.u32.u64 %0, t; }" : "=r"(a) : "l"(p));
    return a;
}
__device__ __forceinline__ unsigned short f2bf(float x) {
    return __bfloat16_as_ushort(__float2bfloat16_rn(x));
}
__device__ __forceinline__ float bf2f(unsigned short u) {
    return __bfloat162float(__ushort_as_bfloat16(u));
}
__device__ __forceinline__ void ldsm_x4(uint32_t* r, uint32_t addr) {
    asm volatile("ldmatrix.sync.aligned.m8n8.x4.shared.b16 {%0,%1,%2,%3}, [%4];"
                 : "=r"(r[0]), "=r"(r[1]), "=r"(r[2]), "=r"(r[3]) : "r"(addr));
}
__device__ __forceinline__ void mma_bf16(float* d, const uint32_t* a, const uint32_t* b) {
    asm volatile("mma.sync.aligned.m16n8k16.row.col.f32.bf16.bf16.f32 "
                 "{%0,%1,%2,%3}, {%4,%5,%6,%7}, {%8,%9}, {%0,%1,%2,%3};"
                 : "+f"(d[0]), "+f"(d[1]), "+f"(d[2]), "+f"(d[3])
                 : "r"(a[0]), "r"(a[1]), "r"(a[2]), "r"(a[3]), "r"(b[0]), "r"(b[1]));
}

// ---------- dtype detection: int64 viewed as int32 has odd words == 0 ----------
__global__ void detect_kernel(const int* __restrict__ idx32) {
    if (threadIdx.x == 0 && blockIdx.x == 0) {
        int is64 = 1;
        #pragma unroll 1
        for (int i = 1; i < 128; i += 2)
            if (idx32[i] != 0) { is64 = 0; break; }
        g_is64 = is64;
    }
}
__device__ __forceinline__ int load_idx(const void* p, int i, int is64) {
    if (is64) return (int)((const long long*)p)[i];
    return ((const int*)p)[i];
}

// ===== weight prep: fp32 W[k][n] -> bf16 hi/lo, stored transposed [n][k], padded rows =====
__global__ void wprep_kernel(const float* __restrict__ w1, const float* __restrict__ w2) {
    int idx = blockIdx.x * blockDim.x + threadIdx.x;   // 4 layers * 2 mats * 16384
    if (idx >= 4 * 2 * DD * DD) return;
    int l = idx / (2 * DD * DD);
    int rem = idx % (2 * DD * DD);
    int m = rem / (DD * DD);
    int kn = rem % (DD * DD);
    int k = kn / DD, nn = kn % DD;
    const float* w = m ? w2 : w1;
    float v = w[(size_t)l * DD * DD + k * DD + nn];
    unsigned short hi = f2bf(v);
    unsigned short lo = f2bf(v - bf2f(hi));
    unsigned char* base = g_wprep + (size_t)l * WL_BYTES + (size_t)m * (2 * MATB);
    uint32_t a = (uint32_t)nn * SAB + (uint32_t)k * 2;
    *(unsigned short*)(base + a)        = hi;
    *(unsigned short*)(base + MATB + a) = lo;
}

// ================= CSR build =================
__global__ void hist_kernel(const void* __restrict__ ei, int* __restrict__ deg, int ne, int n) {
    int e = blockIdx.x * blockDim.x + threadIdx.x;
    if (e >= ne) return;
    const int is64 = g_is64;
    int s = load_idx(ei, e, is64);
    int d = load_idx(ei, ne + e, is64);
    if ((unsigned)s >= (unsigned)n || (unsigned)d >= (unsigned)n) return;
    atomicAdd(deg + d, 1);
}

// block-level exclusive scan (256/block), emit block totals
__global__ void blockscan_kernel(const int* __restrict__ deg, int* __restrict__ off,
                                 int* __restrict__ blk, int n) {
    __shared__ int ws[8];
    int i = blockIdx.x * 256 + threadIdx.x;
    int lane = threadIdx.x & 31, wd = threadIdx.x >> 5;
    int v = (i < n) ? deg[i] : 0;
    int x = v;
    #pragma unroll
    for (int d = 1; d < 32; d <<= 1) {
        int y = __shfl_up_sync(0xffffffffu, x, d);
        if (lane >= d) x += y;
    }
    if (lane == 31) ws[wd] = x;
    __syncthreads();
    if (wd == 0) {
        int s = (lane < 8) ? ws[lane] : 0;
        #pragma unroll
        for (int d = 1; d < 8; d <<= 1) {
            int y = __shfl_up_sync(0xffffffffu, s, d);
            if (lane >= d) s += y;
        }
        if (lane < 8) ws[lane] = s;
    }
    __syncthreads();
    int base = wd ? ws[wd - 1] : 0;
    if (i < n) off[i] = base + x - v;
    if (threadIdx.x == 255) blk[blockIdx.x] = ws[7];
}

// scan block totals (single block, 256 threads), write grand total to off[n]
__global__ void scan2_kernel(int* __restrict__ blk, int* __restrict__ off, int n, int nb) {
    __shared__ int ws[8];
    int t = threadIdx.x;
    int lane = t & 31, wd = t >> 5;
    int v = (t < nb) ? blk[t] : 0;
    int x = v;
    #pragma unroll
    for (int d = 1; d < 32; d <<= 1) {
        int y = __shfl_up_sync(0xffffffffu, x, d);
        if (lane >= d) x += y;
    }
    if (lane == 31) ws[wd] = x;
    __syncthreads();
    if (wd == 0) {
        int s = (lane < 8) ? ws[lane] : 0;
        #pragma unroll
        for (int d = 1; d < 8; d <<= 1) {
            int y = __shfl_up_sync(0xffffffffu, s, d);
            if (lane >= d) s += y;
        }
        if (lane < 8) ws[lane] = s;
    }
    __syncthreads();
    int base = wd ? ws[wd - 1] : 0;
    if (t < nb) blk[t] = base + x - v;     // exclusive block offset
    if (t == 255) off[n] = ws[7];          // grand total
}

// add block offsets, init cur
__global__ void addoff_kernel(int* __restrict__ off, int* __restrict__ cur,
                              const int* __restrict__ blk, int n) {
    int i = blockIdx.x * 256 + threadIdx.x;
    if (i >= n) return;
    int o = off[i] + blk[i >> 8];
    off[i] = o;
    cur[i] = o;
}

__global__ void fill_kernel(const void* __restrict__ ei, int* __restrict__ cur,
                            int* __restrict__ esrc, int ne, int n) {
    int e = blockIdx.x * blockDim.x + threadIdx.x;
    if (e >= ne) return;
    const int is64 = g_is64;
    int s = load_idx(ei, e, is64);
    int d = load_idx(ei, ne + e, is64);
    if ((unsigned)s >= (unsigned)n || (unsigned)d >= (unsigned)n) return;
    int pos = atomicAdd(cur + d, 1);
    esrc[pos] = s;
}

// ================= gather: out[v] = h[v] + sum_{u in N(v)} h[u] =================
// warp per node, unroll-4 edge loop for MLP (4 outstanding L2 loads per lane)
__global__ void gather_kernel(const float* __restrict__ h, const int* __restrict__ off,
                              const int* __restrict__ esrc, float* __restrict__ out, int n) {
    int node = (blockIdx.x * blockDim.x + threadIdx.x) >> 5;
    int lane = threadIdx.x & 31;
    if (node >= n) return;
    int beg = off[node], end = off[node + 1];
    const size_t loff = (size_t)lane * 4;
    float4 a = *(const float4*)(h + (size_t)node * DD + loff);
    int e = beg;
    int m4 = beg + ((end - beg) & ~3);
    #pragma unroll 1
    for (; e < m4; e += 4) {
        int s0 = esrc[e], s1 = esrc[e + 1], s2 = esrc[e + 2], s3 = esrc[e + 3];
        float4 v0 = *(const float4*)(h + (size_t)s0 * DD + loff);
        float4 v1 = *(const float4*)(h + (size_t)s1 * DD + loff);
        float4 v2 = *(const float4*)(h + (size_t)s2 * DD + loff);
        float4 v3 = *(const float4*)(h + (size_t)s3 * DD + loff);
        a.x += v0.x + v1.x + v2.x + v3.x;
        a.y += v0.y + v1.y + v2.y + v3.y;
        a.z += v0.z + v1.z + v2.z + v3.z;
        a.w += v0.w + v1.w + v2.w + v3.w;
    }
    #pragma unroll 1
    for (; e < end; ++e) {
        int s = esrc[e];
        float4 v = *(const float4*)(h + (size_t)s * DD + loff);
        a.x += v.x; a.y += v.y; a.z += v.z; a.w += v.w;
    }
    *(float4*)(out + (size_t)node * DD + loff) = a;
}

// ================= MLP via mma.sync bf16 (3-term hi/lo split) =================
__device__ __forceinline__ void gemm_stage(uint32_t ah0, uint32_t al0,
                                           uint32_t bh_base, uint32_t bl_base,
                                           float acc[2][8][4]) {
    #pragma unroll 1
    for (int kk = 0; kk < 8; ++kk) {
        uint32_t ah[2][4], al[2][4];
        ldsm_x4(ah[0], ah0 + kk * 32);
        ldsm_x4(ah[1], ah0 + 16 * SAB + kk * 32);
        ldsm_x4(al[0], al0 + kk * 32);
        ldsm_x4(al[1], al0 + 16 * SAB + kk * 32);
        #pragma unroll
        for (int np = 0; np < 4; ++np) {
            uint32_t bh[4], bl[4];
            ldsm_x4(bh, bh_base + np * 16 * SAB + kk * 32);
            ldsm_x4(bl, bl_base + np * 16 * SAB + kk * 32);
            #pragma unroll
            for (int t = 0; t < 2; ++t) {
                #pragma unroll
                for (int mt = 0; mt < 2; ++mt) {
                    float* d = acc[mt][2 * np + t];
                    mma_bf16(d, ah[mt], &bh[2 * t]);
                    mma_bf16(d, ah[mt], &bl[2 * t]);
                    mma_bf16(d, al[mt], &bh[2 * t]);
                }
            }
        }
    }
}

// relu_out==1: normal layer, write h(+relu) to out.
// relu_out==0: LAST layer, red-add (h) into pool[batch[row]] directly (no h write).
__global__ void __launch_bounds__(256, 1)
mlp_mma_kernel(const float* __restrict__ in, const unsigned char* __restrict__ wprep,
               const float* __restrict__ b1, const float* __restrict__ b2,
               float* __restrict__ out, const void* __restrict__ batch,
               float* __restrict__ pool, int n, int relu_out)
{
    extern __shared__ char smc[];
    const uint32_t sb = smem_u32(smc);

    const int tid = threadIdx.x;
    const int wid = tid >> 5;
    const int lane = tid & 31;
    const int rg = wid >> 1;          // warp row group (0..3): rows rg*32..+31
    const int cg = wid & 1;           // warp col group (0..1): cols cg*64..+63
    const int is64 = relu_out ? 0 : g_is64;

    // ---- copy prepped weights for this layer (exact smem image) ----
    {
        const uint4* wsrc = (const uint4*)wprep;
        uint4* wdst = (uint4*)(smc + SM_W);
        #pragma unroll 8
        for (int i = tid; i < WL_BYTES / 16; i += 256) wdst[i] = wsrc[i];
    }
    // ---- biases ----
    if (tid < DD) {
        ((float*)(smc + SM_B1))[tid] = b1[tid];
        ((float*)(smc + SM_B2))[tid] = b2[tid];
    }

    // per-lane ldmatrix offsets
    const uint32_t a_off = (uint32_t)(rg * 32 + (lane & 15)) * SAB + ((lane >> 4) << 3) * 2;
    const uint32_t ah0 = sb + SM_AH + a_off;
    const uint32_t al0 = sb + SM_AL + a_off;
    const int g = lane >> 3, ii = lane & 7;
    const uint32_t b_off = (uint32_t)(cg * 64 + ((g >> 1) << 3) + ii) * SAB + ((g & 1) << 3) * 2;

    #pragma unroll 1
    for (int tt = 0; tt < TILES_PER_CTA; ++tt) {
        const int row0 = (blockIdx.x * TILES_PER_CTA + tt) * BM;
        if (row0 >= n) break;
        if (tt > 0) __syncthreads();   // protect A region from previous tile's ldsm readers

        // ---- load A tile, split bf16 hi/lo ----
        {
            int r = tid >> 1;
            int c0 = (tid & 1) * 64;
            bool valid = (row0 + r) < n;
            const float* src = in + (size_t)(row0 + r) * DD + c0;
            char* ah = smc + SM_AH + r * SAB + c0 * 2;
            char* al = smc + SM_AL + r * SAB + c0 * 2;
            #pragma unroll
            for (int c = 0; c < 64; c += 4) {
                float4 v = valid ? *(const float4*)(src + c) : make_float4(0.f, 0.f, 0.f, 0.f);
                unsigned short h0 = f2bf(v.x), h1 = f2bf(v.y), h2 = f2bf(v.z), h3 = f2bf(v.w);
                unsigned short l0 = f2bf(v.x - bf2f(h0)), l1 = f2bf(v.y - bf2f(h1));
                unsigned short l2 = f2bf(v.z - bf2f(h2)), l3 = f2bf(v.w - bf2f(h3));
                *(uint2*)(ah + c * 2) = make_uint2((uint32_t)h0 | ((uint32_t)h1 << 16),
                                                   (uint32_t)h2 | ((uint32_t)h3 << 16));
                *(uint2*)(al + c * 2) = make_uint2((uint32_t)l0 | ((uint32_t)l1 << 16),
                                                   (uint32_t)l2 | ((uint32_t)l3 << 16));
            }
        }
        __syncthreads();   // also covers weight copy on tt==0

        float acc[2][8][4];

        // ======== stage 1: D1 = A @ W1 ========
        #pragma unroll
        for (int mt = 0; mt < 2; ++mt)
            #pragma unroll
            for (int nt = 0; nt < 8; ++nt)
                #pragma unroll
                for (int q = 0; q < 4; ++q) acc[mt][nt][q] = 0.f;

        gemm_stage(ah0, al0, sb + SM_W + b_off, sb + SM_W + MATB + b_off, acc);
        __syncthreads();   // all A reads done before overwrite

        // epilogue 1: z = relu(D1 + b1) -> bf16 hi/lo back into A
        {
            const float* sb1 = (const float*)(smc + SM_B1);
            const int qr = lane >> 2;
            const int qc = (lane & 3) * 2;
            #pragma unroll
            for (int mt = 0; mt < 2; ++mt) {
                #pragma unroll
                for (int nt = 0; nt < 8; ++nt) {
                    int row = rg * 32 + mt * 16 + qr;
                    int col = cg * 64 + nt * 8 + qc;
                    float bj0 = sb1[col], bj1 = sb1[col + 1];
                    float z0 = fmaxf(acc[mt][nt][0] + bj0, 0.f);
                    float z1 = fmaxf(acc[mt][nt][1] + bj1, 0.f);
                    float z2 = fmaxf(acc[mt][nt][2] + bj0, 0.f);
                    float z3 = fmaxf(acc[mt][nt][3] + bj1, 0.f);
                    unsigned short h0 = f2bf(z0), h1 = f2bf(z1), h2 = f2bf(z2), h3 = f2bf(z3);
                    unsigned short l0 = f2bf(z0 - bf2f(h0)), l1 = f2bf(z1 - bf2f(h1));
                    unsigned short l2 = f2bf(z2 - bf2f(h2)), l3 = f2bf(z3 - bf2f(h3));
                    uint32_t o0 = (uint32_t)row * SAB + (uint32_t)col * 2;
                    uint32_t o1 = (uint32_t)(row + 8) * SAB + (uint32_t)col * 2;
                    *(uint32_t*)(smc + SM_AH + o0) = (uint32_t)h0 | ((uint32_t)h1 << 16);
                    *(uint32_t*)(smc + SM_AH + o1) = (uint32_t)h2 | ((uint32_t)h3 << 16);
                    *(uint32_t*)(smc + SM_AL + o0) = (uint32_t)l0 | ((uint32_t)l1 << 16);
                    *(uint32_t*)(smc + SM_AL + o1) = (uint32_t)l2 | ((uint32_t)l3 << 16);
                }
            }
        }
        __syncthreads();

        // ======== stage 2: D2 = Z @ W2 ========
        #pragma unroll
        for (int mt = 0; mt < 2; ++mt)
            #pragma unroll
            for (int nt = 0; nt < 8; ++nt)
                #pragma unroll
                for (int q = 0; q < 4; ++q) acc[mt][nt][q] = 0.f;

        gemm_stage(ah0, al0, sb + SM_W + 2 * MATB + b_off, sb + SM_W + 3 * MATB + b_off, acc);

        // epilogue 2
        {
            const float* sb2 = (const float*)(smc + SM_B2);
            const int qr = lane >> 2;
            const int qc = (lane & 3) * 2;
            #pragma unroll
            for (int mt = 0; mt < 2; ++mt) {
                int row = rg * 32 + mt * 16 + qr;
                int grow0 = row0 + row;
                int grow1 = grow0 + 8;
                if (relu_out) {
                    #pragma unroll
                    for (int nt = 0; nt < 8; ++nt) {
                        int col = cg * 64 + nt * 8 + qc;
                        float bj0 = sb2[col], bj1 = sb2[col + 1];
                        float o0 = fmaxf(acc[mt][nt][0] + bj0, 0.f);
                        float o1 = fmaxf(acc[mt][nt][1] + bj1, 0.f);
                        float o2 = fmaxf(acc[mt][nt][2] + bj0, 0.f);
                        float o3 = fmaxf(acc[mt][nt][3] + bj1, 0.f);
                        if (grow0 < n) *(float2*)(out + (size_t)grow0 * DD + col) = make_float2(o0, o1);
                        if (grow1 < n) *(float2*)(out + (size_t)grow1 * DD + col) = make_float2(o2, o3);
                    }
                } else {
                    // last layer: accumulate straight into pool[batch[row]]
                    int g0 = (grow0 < n) ? load_idx(batch, grow0, is64) : -1;
                    int g1 = (grow1 < n) ? load_idx(batch, grow1, is64) : -1;
                    bool v0 = (unsigned)g0 < (unsigned)NGRAPH;
                    bool v1 = (unsigned)g1 < (unsigned)NGRAPH;
                    #pragma unroll
                    for (int nt = 0; nt < 8; ++nt) {
                        int col = cg * 64 + nt * 8 + qc;
                        float bj0 = sb2[col], bj1 = sb2[col + 1];
                        if (v0) red_add_v2(pool + g0 * DD + col,
                                           acc[mt][nt][0] + bj0, acc[mt][nt][1] + bj1);
                        if (v1) red_add_v2(pool + g1 * DD + col,
                                           acc[mt][nt][2] + bj0, acc[mt][nt][3] + bj1);
                    }
                }
            }
        }
    }
}

// ---------- pooling setup ----------
__global__ void zero_pool_kernel(float* pool, float* cnt) {
    int i = blockIdx.x * blockDim.x + threadIdx.x;
    if (i < NGRAPH * DD) pool[i] = 0.f;
    if (i < NGRAPH) cnt[i] = 0.f;
}

__global__ void cnt_kernel(const void* __restrict__ batch, float* __restrict__ cnt, int n) {
    int i = blockIdx.x * blockDim.x + threadIdx.x;
    if (i >= n) return;
    int g = load_idx(batch, i, g_is64);
    if ((unsigned)g < (unsigned)NGRAPH) atomicAdd(cnt + g, 1.0f);
}

// ---------- finalize: pooled mean + logits ----------
__global__ void finalize_kernel(const float* __restrict__ pool, const float* __restrict__ cnt,
                                const float* __restrict__ wlin, const float* __restrict__ blin,
                                float* __restrict__ out_pooled, float* __restrict__ out_logits) {
    __shared__ float ps[DD];
    int g = blockIdx.x;
    int t = threadIdx.x;
    float c = fmaxf(cnt[g], 1.0f);
    float v = pool[g * DD + t] / c;
    ps[t] = v;
    out_pooled[g * DD + t] = v;
    __syncthreads();
    if (t < NCLASS) {
        float s = blin[t];
        #pragma unroll 4
        for (int k = 0; k < DD; ++k) s += ps[k] * wlin[k * NCLASS + t];
        out_logits[g * NCLASS + t] = s;
    }
}

extern "C" void kernel_launch(void* const* d_in, const int* in_sizes, int n_in,
                              void* d_out, int out_size) {
    const float* x     = (const float*)d_in[0];
    const void*  ei    = d_in[1];
    const void*  batch = d_in[2];
    const float* w1    = (const float*)d_in[3];
    const float* b1    = (const float*)d_in[4];
    const float* w2    = (const float*)d_in[5];
    const float* b2    = (const float*)d_in[6];
    const float* wlin  = (const float*)d_in[7];
    const float* blin  = (const float*)d_in[8];
    float* out = (float*)d_out;

    int n  = in_sizes[0] / DD;
    int ne = in_sizes[1] / 2;
    if (n > NODES_MAX) n = NODES_MAX;
    if (ne > NE_MAX) ne = NE_MAX;

    float *pA, *pB, *pPool, *pCnt, *pScratch;
    int *pDeg, *pOff, *pCur, *pEsrc, *pBlk;
    unsigned char* pW;
    cudaGetSymbolAddress((void**)&pA, g_bufA);
    cudaGetSymbolAddress((void**)&pB, g_bufB);
    cudaGetSymbolAddress((void**)&pPool, g_pool);
    cudaGetSymbolAddress((void**)&pCnt, g_cnt);
    cudaGetSymbolAddress((void**)&pScratch, g_scratch);
    cudaGetSymbolAddress((void**)&pDeg, g_deg);
    cudaGetSymbolAddress((void**)&pOff, g_off);
    cudaGetSymbolAddress((void**)&pCur, g_cur);
    cudaGetSymbolAddress((void**)&pEsrc, g_esrc);
    cudaGetSymbolAddress((void**)&pBlk, g_blk);
    cudaGetSymbolAddress((void**)&pW, g_wprep);

    cudaFuncSetAttribute(mlp_mma_kernel, cudaFuncAttributeMaxDynamicSharedMemorySize, MLP_SMEM);

    const int mlp_grid  = (n + TILES_PER_CTA * BM - 1) / (TILES_PER_CTA * BM);
    const int warp_grid = (n * 32 + 255) / 256;
    const int edge_grid = (ne + 255) / 256;
    const int nb        = (n + 255) / 256;

    detect_kernel<<<1, 32>>>((const int*)ei);
    wprep_kernel<<<(4 * 2 * DD * DD + 255) / 256, 256>>>(w1, w2);

    // ---- CSR build (fast 3-kernel scan) ----
    cudaMemsetAsync(pDeg, 0, (size_t)n * sizeof(int), 0);
    hist_kernel<<<edge_grid, 256>>>(ei, pDeg, ne, n);
    blockscan_kernel<<<nb, 256>>>(pDeg, pOff, pBlk, n);
    scan2_kernel<<<1, 256>>>(pBlk, pOff, n, nb);
    addoff_kernel<<<nb, 256>>>(pOff, pCur, pBlk, n);
    fill_kernel<<<edge_grid, 256>>>(ei, pCur, pEsrc, ne, n);

    // pool buffers ready before last-layer fused pooling
    zero_pool_kernel<<<(NGRAPH * DD + 255) / 256, 256>>>(pPool, pCnt);
    cnt_kernel<<<nb, 256>>>(batch, pCnt, n);

    // separate gather (high occupancy) -> MLP (smem-heavy), per layer
    const float* hcur = x;
    for (int L = 0; L < 4; ++L) {
        gather_kernel<<<warp_grid, 256>>>(hcur, pOff, pEsrc, pB, n);
        mlp_mma_kernel<<<mlp_grid, 256, MLP_SMEM>>>(
            pB, pW + (size_t)L * WL_BYTES, b1 + (size_t)L * DD, b2 + (size_t)L * DD,
            pA, batch, pPool, n, (L < 3) ? 1 : 0);
        hcur = pA;
    }

    float* out_pooled = pScratch;
    float* out_logits = pScratch + NGRAPH * DD;
    if (out_size >= NGRAPH * DD + NGRAPH * NCLASS) {
        out_pooled = out;
        out_logits = out + NGRAPH * DD;
    } else if (out_size == NGRAPH * NCLASS) {
        out_logits = out;
    } else if (out_size == NGRAPH * DD) {
        out_pooled = out;
    }
    finalize_kernel<<<NGRAPH, DD>>>(pPool, pCnt, wlin, blin, out_pooled, out_logits);
}

// round 12
// speedup vs baseline: 1.0642x; 1.0642x over previous
#include <cuda_runtime.h>
#include <cuda_bf16.h>
#include <cstdint>

#define DD 128
#define NODES_MAX 50000
#define NE_MAX 640000
#define NGRAPH 64
#define NCLASS 32
#define BM 128

// ---- smem layout for mma MLP (bytes from dynamic smem base) ----
#define SAB   272                    // bytes per bf16 row (136 elems) -> conflict-free ldmatrix
#define MATB  (128 * SAB)            // 34816 bytes per 128x128 bf16 matrix
#define SM_B1 0
#define SM_B2 512
#define SM_AH 1024
#define SM_AL (SM_AH + MATB)
#define SM_W  (SM_AL + MATB)         // [W1hi|W1lo|W2hi|W2lo]
#define MLP_SMEM (SM_W + 4 * MATB)   // 209920 bytes

#define WL_BYTES (4 * MATB)          // per-layer prepped weights

__device__ float g_bufA[NODES_MAX * DD];
__device__ float g_bufB[NODES_MAX * DD];
__device__ float g_pool[NGRAPH * DD];
__device__ float g_cnt[NGRAPH];
__device__ float g_scratch[NGRAPH * DD + NGRAPH * NCLASS];
__device__ int   g_is64;
__device__ int   g_deg[NODES_MAX];
__device__ int   g_off[NODES_MAX + 1];
__device__ int   g_cur[NODES_MAX];
__device__ int   g_esrc[NE_MAX];
__device__ int   g_blk[256];
__device__ __align__(16) unsigned char g_wprep[4 * WL_BYTES];

// ================= helpers =================
__device__ __forceinline__ void red_add_v2(float* p, float x, float y) {
    asm volatile("red.global.add.v2.f32 [%0], {%1, %2};"
                 :: "l"(p), "f"(x), "f"(y) : "memory");
}
__device__ __forceinline__ uint32_t smem_u32(const void* p) {
    uint32_t a;
    asm("{ .reg .u64 t; cvta.to.shared.u64 t, %1; cvt.u32.u64 %0, t; }" : "=r"(a) : "l"(p));
    return a;
}
__device__ __forceinline__ unsigned short f2bf(float x) {
    return __bfloat16_as_ushort(__float2bfloat16_rn(x));
}
__device__ __forceinline__ float bf2f(unsigned short u) {
    return __bfloat162float(__ushort_as_bfloat16(u));
}
__device__ __forceinline__ void ldsm_x4(uint32_t* r, uint32_t addr) {
    asm volatile("ldmatrix.sync.aligned.m8n8.x4.shared.b16 {%0,%1,%2,%3}, [%4];"
                 : "=r"(r[0]), "=r"(r[1]), "=r"(r[2]), "=r"(r[3]) : "r"(addr));
}
__device__ __forceinline__ void mma_bf16(float* d, const uint32_t* a, const uint32_t* b) {
    asm volatile("mma.sync.aligned.m16n8k16.row.col.f32.bf16.bf16.f32 "
                 "{%0,%1,%2,%3}, {%4,%5,%6,%7}, {%8,%9}, {%0,%1,%2,%3};"
                 : "+f"(d[0]), "+f"(d[1]), "+f"(d[2]), "+f"(d[3])
                 : "r"(a[0]), "r"(a[1]), "r"(a[2]), "r"(a[3]), "r"(b[0]), "r"(b[1]));
}

// ---------- dtype detection: int64 viewed as int32 has odd words == 0 ----------
__global__ void detect_kernel(const int* __restrict__ idx32) {
    if (threadIdx.x == 0 && blockIdx.x == 0) {
        int is64 = 1;
        #pragma unroll 1
        for (int i = 1; i < 128; i += 2)
            if (idx32[i] != 0) { is64 = 0; break; }
        g_is64 = is64;
    }
}
__device__ __forceinline__ int load_idx(const void* p, int i, int is64) {
    if (is64) return (int)((const long long*)p)[i];
    return ((const int*)p)[i];
}

// ===== weight prep: fp32 W[k][n] -> bf16 hi/lo, stored transposed [n][k], padded rows =====
__global__ void wprep_kernel(const float* __restrict__ w1, const float* __restrict__ w2) {
    int idx = blockIdx.x * blockDim.x + threadIdx.x;   // 4 layers * 2 mats * 16384
    if (idx >= 4 * 2 * DD * DD) return;
    int l = idx / (2 * DD * DD);
    int rem = idx % (2 * DD * DD);
    int m = rem / (DD * DD);
    int kn = rem % (DD * DD);
    int k = kn / DD, nn = kn % DD;
    const float* w = m ? w2 : w1;
    float v = w[(size_t)l * DD * DD + k * DD + nn];
    unsigned short hi = f2bf(v);
    unsigned short lo = f2bf(v - bf2f(hi));
    unsigned char* base = g_wprep + (size_t)l * WL_BYTES + (size_t)m * (2 * MATB);
    uint32_t a = (uint32_t)nn * SAB + (uint32_t)k * 2;
    *(unsigned short*)(base + a)        = hi;
    *(unsigned short*)(base + MATB + a) = lo;
}

// ================= CSR build =================
__global__ void hist_kernel(const void* __restrict__ ei, int* __restrict__ deg, int ne, int n) {
    int e = blockIdx.x * blockDim.x + threadIdx.x;
    if (e >= ne) return;
    const int is64 = g_is64;
    int s = load_idx(ei, e, is64);
    int d = load_idx(ei, ne + e, is64);
    if ((unsigned)s >= (unsigned)n || (unsigned)d >= (unsigned)n) return;
    atomicAdd(deg + d, 1);
}

// block-level exclusive scan (256/block), emit block totals
__global__ void blockscan_kernel(const int* __restrict__ deg, int* __restrict__ off,
                                 int* __restrict__ blk, int n) {
    __shared__ int ws[8];
    int i = blockIdx.x * 256 + threadIdx.x;
    int lane = threadIdx.x & 31, wd = threadIdx.x >> 5;
    int v = (i < n) ? deg[i] : 0;
    int x = v;
    #pragma unroll
    for (int d = 1; d < 32; d <<= 1) {
        int y = __shfl_up_sync(0xffffffffu, x, d);
        if (lane >= d) x += y;
    }
    if (lane == 31) ws[wd] = x;
    __syncthreads();
    if (wd == 0) {
        int s = (lane < 8) ? ws[lane] : 0;
        #pragma unroll
        for (int d = 1; d < 8; d <<= 1) {
            int y = __shfl_up_sync(0xffffffffu, s, d);
            if (lane >= d) s += y;
        }
        if (lane < 8) ws[lane] = s;
    }
    __syncthreads();
    int base = wd ? ws[wd - 1] : 0;
    if (i < n) off[i] = base + x - v;
    if (threadIdx.x == 255) blk[blockIdx.x] = ws[7];
}

// scan block totals (single block, 256 threads), write grand total to off[n]
__global__ void scan2_kernel(int* __restrict__ blk, int* __restrict__ off, int n, int nb) {
    __shared__ int ws[8];
    int t = threadIdx.x;
    int lane = t & 31, wd = t >> 5;
    int v = (t < nb) ? blk[t] : 0;
    int x = v;
    #pragma unroll
    for (int d = 1; d < 32; d <<= 1) {
        int y = __shfl_up_sync(0xffffffffu, x, d);
        if (lane >= d) x += y;
    }
    if (lane == 31) ws[wd] = x;
    __syncthreads();
    if (wd == 0) {
        int s = (lane < 8) ? ws[lane] : 0;
        #pragma unroll
        for (int d = 1; d < 8; d <<= 1) {
            int y = __shfl_up_sync(0xffffffffu, s, d);
            if (lane >= d) s += y;
        }
        if (lane < 8) ws[lane] = s;
    }
    __syncthreads();
    int base = wd ? ws[wd - 1] : 0;
    if (t < nb) blk[t] = base + x - v;     // exclusive block offset
    if (t == 255) off[n] = ws[7];          // grand total
}

// add block offsets, init cur
__global__ void addoff_kernel(int* __restrict__ off, int* __restrict__ cur,
                              const int* __restrict__ blk, int n) {
    int i = blockIdx.x * 256 + threadIdx.x;
    if (i >= n) return;
    int o = off[i] + blk[i >> 8];
    off[i] = o;
    cur[i] = o;
}

__global__ void fill_kernel(const void* __restrict__ ei, int* __restrict__ cur,
                            int* __restrict__ esrc, int ne, int n) {
    int e = blockIdx.x * blockDim.x + threadIdx.x;
    if (e >= ne) return;
    const int is64 = g_is64;
    int s = load_idx(ei, e, is64);
    int d = load_idx(ei, ne + e, is64);
    if ((unsigned)s >= (unsigned)n || (unsigned)d >= (unsigned)n) return;
    int pos = atomicAdd(cur + d, 1);
    esrc[pos] = s;
}

// ================= gather: out[v] = h[v] + sum_{u in N(v)} h[u] =================
// warp per node, unroll-4 edge loop for MLP (4 outstanding L2 loads per lane)
__global__ void gather_kernel(const float* __restrict__ h, const int* __restrict__ off,
                              const int* __restrict__ esrc, float* __restrict__ out, int n) {
    int node = (blockIdx.x * blockDim.x + threadIdx.x) >> 5;
    int lane = threadIdx.x & 31;
    if (node >= n) return;
    int beg = off[node], end = off[node + 1];
    const size_t loff = (size_t)lane * 4;
    float4 a = *(const float4*)(h + (size_t)node * DD + loff);
    int e = beg;
    int m4 = beg + ((end - beg) & ~3);
    #pragma unroll 1
    for (; e < m4; e += 4) {
        int s0 = esrc[e], s1 = esrc[e + 1], s2 = esrc[e + 2], s3 = esrc[e + 3];
        float4 v0 = *(const float4*)(h + (size_t)s0 * DD + loff);
        float4 v1 = *(const float4*)(h + (size_t)s1 * DD + loff);
        float4 v2 = *(const float4*)(h + (size_t)s2 * DD + loff);
        float4 v3 = *(const float4*)(h + (size_t)s3 * DD + loff);
        a.x += v0.x + v1.x + v2.x + v3.x;
        a.y += v0.y + v1.y + v2.y + v3.y;
        a.z += v0.z + v1.z + v2.z + v3.z;
        a.w += v0.w + v1.w + v2.w + v3.w;
    }
    #pragma unroll 1
    for (; e < end; ++e) {
        int s = esrc[e];
        float4 v = *(const float4*)(h + (size_t)s * DD + loff);
        a.x += v.x; a.y += v.y; a.z += v.z; a.w += v.w;
    }
    *(float4*)(out + (size_t)node * DD + loff) = a;
}

// ================= MLP via mma.sync bf16 (3-term hi/lo split) =================
__device__ __forceinline__ void gemm_stage(uint32_t ah0, uint32_t al0,
                                           uint32_t bh_base, uint32_t bl_base,
                                           float acc[2][8][4]) {
    #pragma unroll 1
    for (int kk = 0; kk < 8; ++kk) {
        uint32_t ah[2][4], al[2][4];
        ldsm_x4(ah[0], ah0 + kk * 32);
        ldsm_x4(ah[1], ah0 + 16 * SAB + kk * 32);
        ldsm_x4(al[0], al0 + kk * 32);
        ldsm_x4(al[1], al0 + 16 * SAB + kk * 32);
        #pragma unroll
        for (int np = 0; np < 4; ++np) {
            uint32_t bh[4], bl[4];
            ldsm_x4(bh, bh_base + np * 16 * SAB + kk * 32);
            ldsm_x4(bl, bl_base + np * 16 * SAB + kk * 32);
            #pragma unroll
            for (int t = 0; t < 2; ++t) {
                #pragma unroll
                for (int mt = 0; mt < 2; ++mt) {
                    float* d = acc[mt][2 * np + t];
                    mma_bf16(d, ah[mt], &bh[2 * t]);
                    mma_bf16(d, ah[mt], &bl[2 * t]);
                    mma_bf16(d, al[mt], &bh[2 * t]);
                }
            }
        }
    }
}

// relu_out==1: normal layer, write h(+relu) to out.
// relu_out==0: LAST layer, red-add (h) into pool[batch[row]] directly (no h write).
__global__ void __launch_bounds__(256, 1)
mlp_mma_kernel(const float* __restrict__ in, const unsigned char* __restrict__ wprep,
               const float* __restrict__ b1, const float* __restrict__ b2,
               float* __restrict__ out, const void* __restrict__ batch,
               float* __restrict__ pool, int n, int relu_out)
{
    extern __shared__ char smc[];
    const uint32_t sb = smem_u32(smc);

    const int tid = threadIdx.x;
    const int wid = tid >> 5;
    const int lane = tid & 31;
    const int rg = wid >> 1;          // warp row group (0..3): rows rg*32..+31
    const int cg = wid & 1;           // warp col group (0..1): cols cg*64..+63
    const int is64 = relu_out ? 0 : g_is64;
    const int row0 = blockIdx.x * BM;

    // ---- copy prepped weights for this layer (exact smem image) ----
    {
        const uint4* wsrc = (const uint4*)wprep;
        uint4* wdst = (uint4*)(smc + SM_W);
        #pragma unroll 8
        for (int i = tid; i < WL_BYTES / 16; i += 256) wdst[i] = wsrc[i];
    }
    // ---- biases ----
    if (tid < DD) {
        ((float*)(smc + SM_B1))[tid] = b1[tid];
        ((float*)(smc + SM_B2))[tid] = b2[tid];
    }
    // ---- load A tile, split bf16 hi/lo ----
    {
        int r = tid >> 1;
        int c0 = (tid & 1) * 64;
        bool valid = (row0 + r) < n;
        const float* src = in + (size_t)(row0 + r) * DD + c0;
        char* ah = smc + SM_AH + r * SAB + c0 * 2;
        char* al = smc + SM_AL + r * SAB + c0 * 2;
        #pragma unroll
        for (int c = 0; c < 64; c += 4) {
            float4 v = valid ? *(const float4*)(src + c) : make_float4(0.f, 0.f, 0.f, 0.f);
            unsigned short h0 = f2bf(v.x), h1 = f2bf(v.y), h2 = f2bf(v.z), h3 = f2bf(v.w);
            unsigned short l0 = f2bf(v.x - bf2f(h0)), l1 = f2bf(v.y - bf2f(h1));
            unsigned short l2 = f2bf(v.z - bf2f(h2)), l3 = f2bf(v.w - bf2f(h3));
            *(uint2*)(ah + c * 2) = make_uint2((uint32_t)h0 | ((uint32_t)h1 << 16),
                                               (uint32_t)h2 | ((uint32_t)h3 << 16));
            *(uint2*)(al + c * 2) = make_uint2((uint32_t)l0 | ((uint32_t)l1 << 16),
                                               (uint32_t)l2 | ((uint32_t)l3 << 16));
        }
    }
    __syncthreads();

    // per-lane ldmatrix offsets
    const uint32_t a_off = (uint32_t)(rg * 32 + (lane & 15)) * SAB + ((lane >> 4) << 3) * 2;
    const uint32_t ah0 = sb + SM_AH + a_off;
    const uint32_t al0 = sb + SM_AL + a_off;
    {
        const int g = lane >> 3, ii = lane & 7;
        const uint32_t b_off = (uint32_t)(cg * 64 + ((g >> 1) << 3) + ii) * SAB + ((g & 1) << 3) * 2;

        float acc[2][8][4];

        // ======== stage 1: D1 = A @ W1 ========
        #pragma unroll
        for (int mt = 0; mt < 2; ++mt)
            #pragma unroll
            for (int nt = 0; nt < 8; ++nt)
                #pragma unroll
                for (int q = 0; q < 4; ++q) acc[mt][nt][q] = 0.f;

        gemm_stage(ah0, al0, sb + SM_W + b_off, sb + SM_W + MATB + b_off, acc);
        __syncthreads();   // all A reads done before overwrite

        // epilogue 1: z = relu(D1 + b1) -> bf16 hi/lo back into A
        {
            const float* sb1 = (const float*)(smc + SM_B1);
            const int qr = lane >> 2;
            const int qc = (lane & 3) * 2;
            #pragma unroll
            for (int mt = 0; mt < 2; ++mt) {
                #pragma unroll
                for (int nt = 0; nt < 8; ++nt) {
                    int row = rg * 32 + mt * 16 + qr;
                    int col = cg * 64 + nt * 8 + qc;
                    float bj0 = sb1[col], bj1 = sb1[col + 1];
                    float z0 = fmaxf(acc[mt][nt][0] + bj0, 0.f);
                    float z1 = fmaxf(acc[mt][nt][1] + bj1, 0.f);
                    float z2 = fmaxf(acc[mt][nt][2] + bj0, 0.f);
                    float z3 = fmaxf(acc[mt][nt][3] + bj1, 0.f);
                    unsigned short h0 = f2bf(z0), h1 = f2bf(z1), h2 = f2bf(z2), h3 = f2bf(z3);
                    unsigned short l0 = f2bf(z0 - bf2f(h0)), l1 = f2bf(z1 - bf2f(h1));
                    unsigned short l2 = f2bf(z2 - bf2f(h2)), l3 = f2bf(z3 - bf2f(h3));
                    uint32_t o0 = (uint32_t)row * SAB + (uint32_t)col * 2;
                    uint32_t o1 = (uint32_t)(row + 8) * SAB + (uint32_t)col * 2;
                    *(uint32_t*)(smc + SM_AH + o0) = (uint32_t)h0 | ((uint32_t)h1 << 16);
                    *(uint32_t*)(smc + SM_AH + o1) = (uint32_t)h2 | ((uint32_t)h3 << 16);
                    *(uint32_t*)(smc + SM_AL + o0) = (uint32_t)l0 | ((uint32_t)l1 << 16);
                    *(uint32_t*)(smc + SM_AL + o1) = (uint32_t)l2 | ((uint32_t)l3 << 16);
                }
            }
        }
        __syncthreads();

        // ======== stage 2: D2 = Z @ W2 ========
        #pragma unroll
        for (int mt = 0; mt < 2; ++mt)
            #pragma unroll
            for (int nt = 0; nt < 8; ++nt)
                #pragma unroll
                for (int q = 0; q < 4; ++q) acc[mt][nt][q] = 0.f;

        gemm_stage(ah0, al0, sb + SM_W + 2 * MATB + b_off, sb + SM_W + 3 * MATB + b_off, acc);

        // epilogue 2
        {
            const float* sb2 = (const float*)(smc + SM_B2);
            const int qr = lane >> 2;
            const int qc = (lane & 3) * 2;
            #pragma unroll
            for (int mt = 0; mt < 2; ++mt) {
                int row = rg * 32 + mt * 16 + qr;
                int grow0 = row0 + row;
                int grow1 = grow0 + 8;
                if (relu_out) {
                    #pragma unroll
                    for (int nt = 0; nt < 8; ++nt) {
                        int col = cg * 64 + nt * 8 + qc;
                        float bj0 = sb2[col], bj1 = sb2[col + 1];
                        float o0 = fmaxf(acc[mt][nt][0] + bj0, 0.f);
                        float o1 = fmaxf(acc[mt][nt][1] + bj1, 0.f);
                        float o2 = fmaxf(acc[mt][nt][2] + bj0, 0.f);
                        float o3 = fmaxf(acc[mt][nt][3] + bj1, 0.f);
                        if (grow0 < n) *(float2*)(out + (size_t)grow0 * DD + col) = make_float2(o0, o1);
                        if (grow1 < n) *(float2*)(out + (size_t)grow1 * DD + col) = make_float2(o2, o3);
                    }
                } else {
                    // last layer: accumulate straight into pool[batch[row]]
                    int g0 = (grow0 < n) ? load_idx(batch, grow0, is64) : -1;
                    int g1 = (grow1 < n) ? load_idx(batch, grow1, is64) : -1;
                    bool v0 = (unsigned)g0 < (unsigned)NGRAPH;
                    bool v1 = (unsigned)g1 < (unsigned)NGRAPH;
                    #pragma unroll
                    for (int nt = 0; nt < 8; ++nt) {
                        int col = cg * 64 + nt * 8 + qc;
                        float bj0 = sb2[col], bj1 = sb2[col + 1];
                        if (v0) red_add_v2(pool + g0 * DD + col,
                                           acc[mt][nt][0] + bj0, acc[mt][nt][1] + bj1);
                        if (v1) red_add_v2(pool + g1 * DD + col,
                                           acc[mt][nt][2] + bj0, acc[mt][nt][3] + bj1);
                    }
                }
            }
        }
    }
}

// ---------- pooling setup ----------
__global__ void zero_pool_kernel(float* pool, float* cnt) {
    int i = blockIdx.x * blockDim.x + threadIdx.x;
    if (i < NGRAPH * DD) pool[i] = 0.f;
    if (i < NGRAPH) cnt[i] = 0.f;
}

__global__ void cnt_kernel(const void* __restrict__ batch, float* __restrict__ cnt, int n) {
    int i = blockIdx.x * blockDim.x + threadIdx.x;
    if (i >= n) return;
    int g = load_idx(batch, i, g_is64);
    if ((unsigned)g < (unsigned)NGRAPH) atomicAdd(cnt + g, 1.0f);
}

// ---------- finalize: pooled mean + logits ----------
__global__ void finalize_kernel(const float* __restrict__ pool, const float* __restrict__ cnt,
                                const float* __restrict__ wlin, const float* __restrict__ blin,
                                float* __restrict__ out_pooled, float* __restrict__ out_logits) {
    __shared__ float ps[DD];
    int g = blockIdx.x;
    int t = threadIdx.x;
    float c = fmaxf(cnt[g], 1.0f);
    float v = pool[g * DD + t] / c;
    ps[t] = v;
    out_pooled[g * DD + t] = v;
    __syncthreads();
    if (t < NCLASS) {
        float s = blin[t];
        #pragma unroll 4
        for (int k = 0; k < DD; ++k) s += ps[k] * wlin[k * NCLASS + t];
        out_logits[g * NCLASS + t] = s;
    }
}

extern "C" void kernel_launch(void* const* d_in, const int* in_sizes, int n_in,
                              void* d_out, int out_size) {
    const float* x     = (const float*)d_in[0];
    const void*  ei    = d_in[1];
    const void*  batch = d_in[2];
    const float* w1    = (const float*)d_in[3];
    const float* b1    = (const float*)d_in[4];
    const float* w2    = (const float*)d_in[5];
    const float* b2    = (const float*)d_in[6];
    const float* wlin  = (const float*)d_in[7];
    const float* blin  = (const float*)d_in[8];
    float* out = (float*)d_out;

    int n  = in_sizes[0] / DD;
    int ne = in_sizes[1] / 2;
    if (n > NODES_MAX) n = NODES_MAX;
    if (ne > NE_MAX) ne = NE_MAX;

    float *pA, *pB, *pPool, *pCnt, *pScratch;
    int *pDeg, *pOff, *pCur, *pEsrc, *pBlk;
    unsigned char* pW;
    cudaGetSymbolAddress((void**)&pA, g_bufA);
    cudaGetSymbolAddress((void**)&pB, g_bufB);
    cudaGetSymbolAddress((void**)&pPool, g_pool);
    cudaGetSymbolAddress((void**)&pCnt, g_cnt);
    cudaGetSymbolAddress((void**)&pScratch, g_scratch);
    cudaGetSymbolAddress((void**)&pDeg, g_deg);
    cudaGetSymbolAddress((void**)&pOff, g_off);
    cudaGetSymbolAddress((void**)&pCur, g_cur);
    cudaGetSymbolAddress((void**)&pEsrc, g_esrc);
    cudaGetSymbolAddress((void**)&pBlk, g_blk);
    cudaGetSymbolAddress((void**)&pW, g_wprep);

    cudaFuncSetAttribute(mlp_mma_kernel, cudaFuncAttributeMaxDynamicSharedMemorySize, MLP_SMEM);

    const int mlp_grid  = (n + BM - 1) / BM;
    const int warp_grid = (n * 32 + 255) / 256;
    const int edge_grid = (ne + 255) / 256;
    const int nb        = (n + 255) / 256;

    detect_kernel<<<1, 32>>>((const int*)ei);
    wprep_kernel<<<(4 * 2 * DD * DD + 255) / 256, 256>>>(w1, w2);

    // ---- CSR build (fast 3-kernel scan) ----
    cudaMemsetAsync(pDeg, 0, (size_t)n * sizeof(int), 0);
    hist_kernel<<<edge_grid, 256>>>(ei, pDeg, ne, n);
    blockscan_kernel<<<nb, 256>>>(pDeg, pOff, pBlk, n);
    scan2_kernel<<<1, 256>>>(pBlk, pOff, n, nb);
    addoff_kernel<<<nb, 256>>>(pOff, pCur, pBlk, n);
    fill_kernel<<<edge_grid, 256>>>(ei, pCur, pEsrc, ne, n);

    // pool buffers ready before last-layer fused pooling
    zero_pool_kernel<<<(NGRAPH * DD + 255) / 256, 256>>>(pPool, pCnt);
    cnt_kernel<<<nb, 256>>>(batch, pCnt, n);

    // separate gather (high occupancy) -> MLP (smem-heavy), per layer
    const float* hcur = x;
    for (int L = 0; L < 4; ++L) {
        gather_kernel<<<warp_grid, 256>>>(hcur, pOff, pEsrc, pB, n);
        mlp_mma_kernel<<<mlp_grid, 256, MLP_SMEM>>>(
            pB, pW + (size_t)L * WL_BYTES, b1 + (size_t)L * DD, b2 + (size_t)L * DD,
            pA, batch, pPool, n, (L < 3) ? 1 : 0);
        hcur = pA;
    }

    float* out_pooled = pScratch;
    float* out_logits = pScratch + NGRAPH * DD;
    if (out_size >= NGRAPH * DD + NGRAPH * NCLASS) {
        out_pooled = out;
        out_logits = out + NGRAPH * DD;
    } else if (out_size == NGRAPH * NCLASS) {
        out_logits = out;
    } else if (out_size == NGRAPH * DD) {
        out_pooled = out;
    }
    finalize_kernel<<<NGRAPH, DD>>>(pPool, pCnt, wlin, blin, out_pooled, out_logits);
}

// round 13
// speedup vs baseline: 1.0935x; 1.0276x over previous
#include <cuda_runtime.h>
#include <cuda_bf16.h>
#include <cstdint>

#define DD 128
#define NODES_MAX 50000
#define NE_MAX 640000
#define NGRAPH 64
#define NCLASS 32
#define BM 128

// ---- smem layout for mma MLP (bytes from dynamic smem base) ----
#define SAB   272                    // bytes per bf16 row (136 elems) -> conflict-free ldmatrix
#define MATB  (128 * SAB)            // 34816 bytes per 128x128 bf16 matrix
#define SM_B1 0
#define SM_B2 512
#define SM_AH 1024
#define SM_AL (SM_AH + MATB)
#define SM_W  (SM_AL + MATB)         // [W1hi|W1lo|W2hi|W2lo]
#define MLP_SMEM (SM_W + 4 * MATB)   // 209920 bytes

#define WL_BYTES (4 * MATB)          // per-layer prepped weights

__device__ float g_bufB[NODES_MAX * DD];                 // fp32 aggregation buffer
__device__ unsigned short g_h16[NODES_MAX * DD];         // bf16 hidden state
__device__ float g_pool[NGRAPH * DD];
__device__ float g_cnt[NGRAPH];
__device__ float g_scratch[NGRAPH * DD + NGRAPH * NCLASS];
__device__ int   g_is64;
__device__ int   g_deg[NODES_MAX];
__device__ int   g_off[NODES_MAX + 1];
__device__ int   g_cur[NODES_MAX];
__device__ int   g_esrc[NE_MAX];
__device__ int   g_blk[256];
__device__ __align__(16) unsigned char g_wprep[4 * WL_BYTES];

// ================= helpers =================
__device__ __forceinline__ void red_add_v2(float* p, float x, float y) {
    asm volatile("red.global.add.v2.f32 [%0], {%1, %2};"
                 :: "l"(p), "f"(x), "f"(y) : "memory");
}
__device__ __forceinline__ uint32_t smem_u32(const void* p) {
    uint32_t a;
    asm("{ .reg .u64 t; cvta.to.shared.u64 t, %1; cvt.u32.u64 %0, t; }" : "=r"(a) : "l"(p));
    return a;
}
__device__ __forceinline__ unsigned short f2bf(float x) {
    return __bfloat16_as_ushort(__float2bfloat16_rn(x));
}
__device__ __forceinline__ float bf2f(unsigned short u) {
    return __bfloat162float(__ushort_as_bfloat16(u));
}
__device__ __forceinline__ void ldsm_x4(uint32_t* r, uint32_t addr) {
    asm volatile("ldmatrix.sync.aligned.m8n8.x4.shared.b16 {%0,%1,%2,%3}, [%4];"
                 : "=r"(r[0]), "=r"(r[1]), "=r"(r[2]), "=r"(r[3]) : "r"(addr));
}
__device__ __forceinline__ void mma_bf16(float* d, const uint32_t* a, const uint32_t* b) {
    asm volatile("mma.sync.aligned.m16n8k16.row.col.f32.bf16.bf16.f32 "
                 "{%0,%1,%2,%3}, {%4,%5,%6,%7}, {%8,%9}, {%0,%1,%2,%3};"
                 : "+f"(d[0]), "+f"(d[1]), "+f"(d[2]), "+f"(d[3])
                 : "r"(a[0]), "r"(a[1]), "r"(a[2]), "r"(a[3]), "r"(b[0]), "r"(b[1]));
}

// ---------- dtype detection: int64 viewed as int32 has odd words == 0 ----------
__global__ void detect_kernel(const int* __restrict__ idx32) {
    if (threadIdx.x == 0 && blockIdx.x == 0) {
        int is64 = 1;
        #pragma unroll 1
        for (int i = 1; i < 128; i += 2)
            if (idx32[i] != 0) { is64 = 0; break; }
        g_is64 = is64;
    }
}
__device__ __forceinline__ int load_idx(const void* p, int i, int is64) {
    if (is64) return (int)((const long long*)p)[i];
    return ((const int*)p)[i];
}

// ===== weight prep + zero deg/pool/cnt (one launch) =====
__global__ void wprep_kernel(const float* __restrict__ w1, const float* __restrict__ w2, int n) {
    int idx = blockIdx.x * blockDim.x + threadIdx.x;   // 131072 threads
    if (idx < n) g_deg[idx] = 0;
    if (idx < NGRAPH * DD) g_pool[idx] = 0.f;
    if (idx < NGRAPH) g_cnt[idx] = 0.f;
    if (idx >= 4 * 2 * DD * DD) return;
    int l = idx / (2 * DD * DD);
    int rem = idx % (2 * DD * DD);
    int m = rem / (DD * DD);
    int kn = rem % (DD * DD);
    int k = kn / DD, nn = kn % DD;
    const float* w = m ? w2 : w1;
    float v = w[(size_t)l * DD * DD + k * DD + nn];
    unsigned short hi = f2bf(v);
    unsigned short lo = f2bf(v - bf2f(hi));
    unsigned char* base = g_wprep + (size_t)l * WL_BYTES + (size_t)m * (2 * MATB);
    uint32_t a = (uint32_t)nn * SAB + (uint32_t)k * 2;
    *(unsigned short*)(base + a)        = hi;
    *(unsigned short*)(base + MATB + a) = lo;
}

// ================= CSR build =================
__global__ void hist_kernel(const void* __restrict__ ei, int* __restrict__ deg, int ne, int n) {
    int e = blockIdx.x * blockDim.x + threadIdx.x;
    if (e >= ne) return;
    const int is64 = g_is64;
    int s = load_idx(ei, e, is64);
    int d = load_idx(ei, ne + e, is64);
    if ((unsigned)s >= (unsigned)n || (unsigned)d >= (unsigned)n) return;
    atomicAdd(deg + d, 1);
}

// block-level exclusive scan (256/block), emit block totals
__global__ void blockscan_kernel(const int* __restrict__ deg, int* __restrict__ off,
                                 int* __restrict__ blk, int n) {
    __shared__ int ws[8];
    int i = blockIdx.x * 256 + threadIdx.x;
    int lane = threadIdx.x & 31, wd = threadIdx.x >> 5;
    int v = (i < n) ? deg[i] : 0;
    int x = v;
    #pragma unroll
    for (int d = 1; d < 32; d <<= 1) {
        int y = __shfl_up_sync(0xffffffffu, x, d);
        if (lane >= d) x += y;
    }
    if (lane == 31) ws[wd] = x;
    __syncthreads();
    if (wd == 0) {
        int s = (lane < 8) ? ws[lane] : 0;
        #pragma unroll
        for (int d = 1; d < 8; d <<= 1) {
            int y = __shfl_up_sync(0xffffffffu, s, d);
            if (lane >= d) s += y;
        }
        if (lane < 8) ws[lane] = s;
    }
    __syncthreads();
    int base = wd ? ws[wd - 1] : 0;
    if (i < n) off[i] = base + x - v;
    if (threadIdx.x == 255) blk[blockIdx.x] = ws[7];
}

// scan block totals (single block, 256 threads), write grand total to off[n]
__global__ void scan2_kernel(int* __restrict__ blk, int* __restrict__ off, int n, int nb) {
    __shared__ int ws[8];
    int t = threadIdx.x;
    int lane = t & 31, wd = t >> 5;
    int v = (t < nb) ? blk[t] : 0;
    int x = v;
    #pragma unroll
    for (int d = 1; d < 32; d <<= 1) {
        int y = __shfl_up_sync(0xffffffffu, x, d);
        if (lane >= d) x += y;
    }
    if (lane == 31) ws[wd] = x;
    __syncthreads();
    if (wd == 0) {
        int s = (lane < 8) ? ws[lane] : 0;
        #pragma unroll
        for (int d = 1; d < 8; d <<= 1) {
            int y = __shfl_up_sync(0xffffffffu, s, d);
            if (lane >= d) s += y;
        }
        if (lane < 8) ws[lane] = s;
    }
    __syncthreads();
    int base = wd ? ws[wd - 1] : 0;
    if (t < nb) blk[t] = base + x - v;     // exclusive block offset
    if (t == 255) off[n] = ws[7];          // grand total
}

// add block offsets, init cur, count graph sizes
__global__ void addoff_kernel(int* __restrict__ off, int* __restrict__ cur,
                              const int* __restrict__ blk, const void* __restrict__ batch,
                              float* __restrict__ cnt, int n) {
    int i = blockIdx.x * 256 + threadIdx.x;
    if (i >= n) return;
    int o = off[i] + blk[i >> 8];
    off[i] = o;
    cur[i] = o;
    int g = load_idx(batch, i, g_is64);
    if ((unsigned)g < (unsigned)NGRAPH) atomicAdd(cnt + g, 1.0f);
}

__global__ void fill_kernel(const void* __restrict__ ei, int* __restrict__ cur,
                            int* __restrict__ esrc, int ne, int n) {
    int e = blockIdx.x * blockDim.x + threadIdx.x;
    if (e >= ne) return;
    const int is64 = g_is64;
    int s = load_idx(ei, e, is64);
    int d = load_idx(ei, ne + e, is64);
    if ((unsigned)s >= (unsigned)n || (unsigned)d >= (unsigned)n) return;
    int pos = atomicAdd(cur + d, 1);
    esrc[pos] = s;
}

// ================= gather: out[v] = h[v] + sum_{u in N(v)} h[u] =================
// warp per node, unroll-4 edge loop. use16: read bf16 h (half traffic), else fp32.
__global__ void gather_kernel(const float* __restrict__ hf, const unsigned short* __restrict__ h16,
                              const int* __restrict__ off, const int* __restrict__ esrc,
                              float* __restrict__ out, int n, int use16) {
    int node = (blockIdx.x * blockDim.x + threadIdx.x) >> 5;
    int lane = threadIdx.x & 31;
    if (node >= n) return;
    int beg = off[node], end = off[node + 1];
    float4 a;
    if (use16) {
        const size_t loff = (size_t)lane * 4;
        uint2 u = *(const uint2*)(h16 + (size_t)node * DD + loff);
        a.x = bf2f((unsigned short)u.x); a.y = bf2f((unsigned short)(u.x >> 16));
        a.z = bf2f((unsigned short)u.y); a.w = bf2f((unsigned short)(u.y >> 16));
        int e = beg;
        int m4 = beg + ((end - beg) & ~3);
        #pragma unroll 1
        for (; e < m4; e += 4) {
            int s0 = esrc[e], s1 = esrc[e + 1], s2 = esrc[e + 2], s3 = esrc[e + 3];
            uint2 u0 = *(const uint2*)(h16 + (size_t)s0 * DD + loff);
            uint2 u1 = *(const uint2*)(h16 + (size_t)s1 * DD + loff);
            uint2 u2 = *(const uint2*)(h16 + (size_t)s2 * DD + loff);
            uint2 u3 = *(const uint2*)(h16 + (size_t)s3 * DD + loff);
            a.x += bf2f((unsigned short)u0.x) + bf2f((unsigned short)u1.x)
                 + bf2f((unsigned short)u2.x) + bf2f((unsigned short)u3.x);
            a.y += bf2f((unsigned short)(u0.x >> 16)) + bf2f((unsigned short)(u1.x >> 16))
                 + bf2f((unsigned short)(u2.x >> 16)) + bf2f((unsigned short)(u3.x >> 16));
            a.z += bf2f((unsigned short)u0.y) + bf2f((unsigned short)u1.y)
                 + bf2f((unsigned short)u2.y) + bf2f((unsigned short)u3.y);
            a.w += bf2f((unsigned short)(u0.y >> 16)) + bf2f((unsigned short)(u1.y >> 16))
                 + bf2f((unsigned short)(u2.y >> 16)) + bf2f((unsigned short)(u3.y >> 16));
        }
        #pragma unroll 1
        for (; e < end; ++e) {
            int s = esrc[e];
            uint2 u = *(const uint2*)(h16 + (size_t)s * DD + loff);
            a.x += bf2f((unsigned short)u.x); a.y += bf2f((unsigned short)(u.x >> 16));
            a.z += bf2f((unsigned short)u.y); a.w += bf2f((unsigned short)(u.y >> 16));
        }
    } else {
        const size_t loff = (size_t)lane * 4;
        a = *(const float4*)(hf + (size_t)node * DD + loff);
        int e = beg;
        int m4 = beg + ((end - beg) & ~3);
        #pragma unroll 1
        for (; e < m4; e += 4) {
            int s0 = esrc[e], s1 = esrc[e + 1], s2 = esrc[e + 2], s3 = esrc[e + 3];
            float4 v0 = *(const float4*)(hf + (size_t)s0 * DD + loff);
            float4 v1 = *(const float4*)(hf + (size_t)s1 * DD + loff);
            float4 v2 = *(const float4*)(hf + (size_t)s2 * DD + loff);
            float4 v3 = *(const float4*)(hf + (size_t)s3 * DD + loff);
            a.x += v0.x + v1.x + v2.x + v3.x;
            a.y += v0.y + v1.y + v2.y + v3.y;
            a.z += v0.z + v1.z + v2.z + v3.z;
            a.w += v0.w + v1.w + v2.w + v3.w;
        }
        #pragma unroll 1
        for (; e < end; ++e) {
            int s = esrc[e];
            float4 v = *(const float4*)(hf + (size_t)s * DD + loff);
            a.x += v.x; a.y += v.y; a.z += v.z; a.w += v.w;
        }
    }
    *(float4*)(out + (size_t)node * DD + (size_t)lane * 4) = a;
}

// ================= MLP via mma.sync bf16 (3-term hi/lo split) =================
__device__ __forceinline__ void gemm_stage(uint32_t ah0, uint32_t al0,
                                           uint32_t bh_base, uint32_t bl_base,
                                           float acc[2][8][4]) {
    #pragma unroll 1
    for (int kk = 0; kk < 8; ++kk) {
        uint32_t ah[2][4], al[2][4];
        ldsm_x4(ah[0], ah0 + kk * 32);
        ldsm_x4(ah[1], ah0 + 16 * SAB + kk * 32);
        ldsm_x4(al[0], al0 + kk * 32);
        ldsm_x4(al[1], al0 + 16 * SAB + kk * 32);
        #pragma unroll
        for (int np = 0; np < 4; ++np) {
            uint32_t bh[4], bl[4];
            ldsm_x4(bh, bh_base + np * 16 * SAB + kk * 32);
            ldsm_x4(bl, bl_base + np * 16 * SAB + kk * 32);
            #pragma unroll
            for (int t = 0; t < 2; ++t) {
                #pragma unroll
                for (int mt = 0; mt < 2; ++mt) {
                    float* d = acc[mt][2 * np + t];
                    mma_bf16(d, ah[mt], &bh[2 * t]);
                    mma_bf16(d, ah[mt], &bl[2 * t]);
                    mma_bf16(d, al[mt], &bh[2 * t]);
                }
            }
        }
    }
}

// relu_out==1: write relu(h) as bf16 to out16.
// relu_out==0: LAST layer, red-add h into pool[batch[row]] (no h write).
__global__ void __launch_bounds__(256, 1)
mlp_mma_kernel(const float* __restrict__ in, const unsigned char* __restrict__ wprep,
               const float* __restrict__ b1, const float* __restrict__ b2,
               unsigned short* __restrict__ out16, const void* __restrict__ batch,
               float* __restrict__ pool, int n, int relu_out)
{
    extern __shared__ char smc[];
    const uint32_t sb = smem_u32(smc);

    const int tid = threadIdx.x;
    const int wid = tid >> 5;
    const int lane = tid & 31;
    const int rg = wid >> 1;          // warp row group (0..3): rows rg*32..+31
    const int cg = wid & 1;           // warp col group (0..1): cols cg*64..+63
    const int is64 = relu_out ? 0 : g_is64;
    const int row0 = blockIdx.x * BM;

    // ---- copy prepped weights for this layer (exact smem image) ----
    {
        const uint4* wsrc = (const uint4*)wprep;
        uint4* wdst = (uint4*)(smc + SM_W);
        #pragma unroll 8
        for (int i = tid; i < WL_BYTES / 16; i += 256) wdst[i] = wsrc[i];
    }
    // ---- biases ----
    if (tid < DD) {
        ((float*)(smc + SM_B1))[tid] = b1[tid];
        ((float*)(smc + SM_B2))[tid] = b2[tid];
    }
    // ---- load A tile (fp32 agg), split bf16 hi/lo ----
    {
        int r = tid >> 1;
        int c0 = (tid & 1) * 64;
        bool valid = (row0 + r) < n;
        const float* src = in + (size_t)(row0 + r) * DD + c0;
        char* ah = smc + SM_AH + r * SAB + c0 * 2;
        char* al = smc + SM_AL + r * SAB + c0 * 2;
        #pragma unroll
        for (int c = 0; c < 64; c += 4) {
            float4 v = valid ? *(const float4*)(src + c) : make_float4(0.f, 0.f, 0.f, 0.f);
            unsigned short h0 = f2bf(v.x), h1 = f2bf(v.y), h2 = f2bf(v.z), h3 = f2bf(v.w);
            unsigned short l0 = f2bf(v.x - bf2f(h0)), l1 = f2bf(v.y - bf2f(h1));
            unsigned short l2 = f2bf(v.z - bf2f(h2)), l3 = f2bf(v.w - bf2f(h3));
            *(uint2*)(ah + c * 2) = make_uint2((uint32_t)h0 | ((uint32_t)h1 << 16),
                                               (uint32_t)h2 | ((uint32_t)h3 << 16));
            *(uint2*)(al + c * 2) = make_uint2((uint32_t)l0 | ((uint32_t)l1 << 16),
                                               (uint32_t)l2 | ((uint32_t)l3 << 16));
        }
    }
    __syncthreads();

    // per-lane ldmatrix offsets
    const uint32_t a_off = (uint32_t)(rg * 32 + (lane & 15)) * SAB + ((lane >> 4) << 3) * 2;
    const uint32_t ah0 = sb + SM_AH + a_off;
    const uint32_t al0 = sb + SM_AL + a_off;
    {
        const int g = lane >> 3, ii = lane & 7;
        const uint32_t b_off = (uint32_t)(cg * 64 + ((g >> 1) << 3) + ii) * SAB + ((g & 1) << 3) * 2;

        float acc[2][8][4];

        // ======== stage 1: D1 = A @ W1 ========
        #pragma unroll
        for (int mt = 0; mt < 2; ++mt)
            #pragma unroll
            for (int nt = 0; nt < 8; ++nt)
                #pragma unroll
                for (int q = 0; q < 4; ++q) acc[mt][nt][q] = 0.f;

        gemm_stage(ah0, al0, sb + SM_W + b_off, sb + SM_W + MATB + b_off, acc);
        __syncthreads();   // all A reads done before overwrite

        // epilogue 1: z = relu(D1 + b1) -> bf16 hi/lo back into A
        {
            const float* sb1 = (const float*)(smc + SM_B1);
            const int qr = lane >> 2;
            const int qc = (lane & 3) * 2;
            #pragma unroll
            for (int mt = 0; mt < 2; ++mt) {
                #pragma unroll
                for (int nt = 0; nt < 8; ++nt) {
                    int row = rg * 32 + mt * 16 + qr;
                    int col = cg * 64 + nt * 8 + qc;
                    float bj0 = sb1[col], bj1 = sb1[col + 1];
                    float z0 = fmaxf(acc[mt][nt][0] + bj0, 0.f);
                    float z1 = fmaxf(acc[mt][nt][1] + bj1, 0.f);
                    float z2 = fmaxf(acc[mt][nt][2] + bj0, 0.f);
                    float z3 = fmaxf(acc[mt][nt][3] + bj1, 0.f);
                    unsigned short h0 = f2bf(z0), h1 = f2bf(z1), h2 = f2bf(z2), h3 = f2bf(z3);
                    unsigned short l0 = f2bf(z0 - bf2f(h0)), l1 = f2bf(z1 - bf2f(h1));
                    unsigned short l2 = f2bf(z2 - bf2f(h2)), l3 = f2bf(z3 - bf2f(h3));
                    uint32_t o0 = (uint32_t)row * SAB + (uint32_t)col * 2;
                    uint32_t o1 = (uint32_t)(row + 8) * SAB + (uint32_t)col * 2;
                    *(uint32_t*)(smc + SM_AH + o0) = (uint32_t)h0 | ((uint32_t)h1 << 16);
                    *(uint32_t*)(smc + SM_AH + o1) = (uint32_t)h2 | ((uint32_t)h3 << 16);
                    *(uint32_t*)(smc + SM_AL + o0) = (uint32_t)l0 | ((uint32_t)l1 << 16);
                    *(uint32_t*)(smc + SM_AL + o1) = (uint32_t)l2 | ((uint32_t)l3 << 16);
                }
            }
        }
        __syncthreads();

        // ======== stage 2: D2 = Z @ W2 ========
        #pragma unroll
        for (int mt = 0; mt < 2; ++mt)
            #pragma unroll
            for (int nt = 0; nt < 8; ++nt)
                #pragma unroll
                for (int q = 0; q < 4; ++q) acc[mt][nt][q] = 0.f;

        gemm_stage(ah0, al0, sb + SM_W + 2 * MATB + b_off, sb + SM_W + 3 * MATB + b_off, acc);

        // epilogue 2
        {
            const float* sb2 = (const float*)(smc + SM_B2);
            const int qr = lane >> 2;
            const int qc = (lane & 3) * 2;
            #pragma unroll
            for (int mt = 0; mt < 2; ++mt) {
                int row = rg * 32 + mt * 16 + qr;
                int grow0 = row0 + row;
                int grow1 = grow0 + 8;
                if (relu_out) {
                    #pragma unroll
                    for (int nt = 0; nt < 8; ++nt) {
                        int col = cg * 64 + nt * 8 + qc;
                        float bj0 = sb2[col], bj1 = sb2[col + 1];
                        float o0 = fmaxf(acc[mt][nt][0] + bj0, 0.f);
                        float o1 = fmaxf(acc[mt][nt][1] + bj1, 0.f);
                        float o2 = fmaxf(acc[mt][nt][2] + bj0, 0.f);
                        float o3 = fmaxf(acc[mt][nt][3] + bj1, 0.f);
                        if (grow0 < n)
                            *(uint32_t*)(out16 + (size_t)grow0 * DD + col) =
                                (uint32_t)f2bf(o0) | ((uint32_t)f2bf(o1) << 16);
                        if (grow1 < n)
                            *(uint32_t*)(out16 + (size_t)grow1 * DD + col) =
                                (uint32_t)f2bf(o2) | ((uint32_t)f2bf(o3) << 16);
                    }
                } else {
                    // last layer: accumulate straight into pool[batch[row]] (fp32, exact path)
                    int g0 = (grow0 < n) ? load_idx(batch, grow0, is64) : -1;
                    int g1 = (grow1 < n) ? load_idx(batch, grow1, is64) : -1;
                    bool v0 = (unsigned)g0 < (unsigned)NGRAPH;
                    bool v1 = (unsigned)g1 < (unsigned)NGRAPH;
                    #pragma unroll
                    for (int nt = 0; nt < 8; ++nt) {
                        int col = cg * 64 + nt * 8 + qc;
                        float bj0 = sb2[col], bj1 = sb2[col + 1];
                        if (v0) red_add_v2(pool + g0 * DD + col,
                                           acc[mt][nt][0] + bj0, acc[mt][nt][1] + bj1);
                        if (v1) red_add_v2(pool + g1 * DD + col,
                                           acc[mt][nt][2] + bj0, acc[mt][nt][3] + bj1);
                    }
                }
            }
        }
    }
}

// ---------- finalize: pooled mean + logits ----------
__global__ void finalize_kernel(const float* __restrict__ pool, const float* __restrict__ cnt,
                                const float* __restrict__ wlin, const float* __restrict__ blin,
                                float* __restrict__ out_pooled, float* __restrict__ out_logits) {
    __shared__ float ps[DD];
    int g = blockIdx.x;
    int t = threadIdx.x;
    float c = fmaxf(cnt[g], 1.0f);
    float v = pool[g * DD + t] / c;
    ps[t] = v;
    out_pooled[g * DD + t] = v;
    __syncthreads();
    if (t < NCLASS) {
        float s = blin[t];
        #pragma unroll 4
        for (int k = 0; k < DD; ++k) s += ps[k] * wlin[k * NCLASS + t];
        out_logits[g * NCLASS + t] = s;
    }
}

extern "C" void kernel_launch(void* const* d_in, const int* in_sizes, int n_in,
                              void* d_out, int out_size) {
    const float* x     = (const float*)d_in[0];
    const void*  ei    = d_in[1];
    const void*  batch = d_in[2];
    const float* w1    = (const float*)d_in[3];
    const float* b1    = (const float*)d_in[4];
    const float* w2    = (const float*)d_in[5];
    const float* b2    = (const float*)d_in[6];
    const float* wlin  = (const float*)d_in[7];
    const float* blin  = (const float*)d_in[8];
    float* out = (float*)d_out;

    int n  = in_sizes[0] / DD;
    int ne = in_sizes[1] / 2;
    if (n > NODES_MAX) n = NODES_MAX;
    if (ne > NE_MAX) ne = NE_MAX;

    float *pB, *pPool, *pCnt, *pScratch;
    unsigned short* pH16;
    int *pDeg, *pOff, *pCur, *pEsrc, *pBlk;
    unsigned char* pW;
    cudaGetSymbolAddress((void**)&pB, g_bufB);
    cudaGetSymbolAddress((void**)&pH16, g_h16);
    cudaGetSymbolAddress((void**)&pPool, g_pool);
    cudaGetSymbolAddress((void**)&pCnt, g_cnt);
    cudaGetSymbolAddress((void**)&pScratch, g_scratch);
    cudaGetSymbolAddress((void**)&pDeg, g_deg);
    cudaGetSymbolAddress((void**)&pOff, g_off);
    cudaGetSymbolAddress((void**)&pCur, g_cur);
    cudaGetSymbolAddress((void**)&pEsrc, g_esrc);
    cudaGetSymbolAddress((void**)&pBlk, g_blk);
    cudaGetSymbolAddress((void**)&pW, g_wprep);

    cudaFuncSetAttribute(mlp_mma_kernel, cudaFuncAttributeMaxDynamicSharedMemorySize, MLP_SMEM);

    const int mlp_grid  = (n + BM - 1) / BM;
    const int warp_grid = (n * 32 + 255) / 256;
    const int edge_grid = (ne + 255) / 256;
    const int nb        = (n + 255) / 256;

    detect_kernel<<<1, 32>>>((const int*)ei);
    wprep_kernel<<<512, 256>>>(w1, w2, n);   // also zeroes deg/pool/cnt

    // ---- CSR build (fast 3-kernel scan) ----
    hist_kernel<<<edge_grid, 256>>>(ei, pDeg, ne, n);
    blockscan_kernel<<<nb, 256>>>(pDeg, pOff, pBlk, n);
    scan2_kernel<<<1, 256>>>(pBlk, pOff, n, nb);
    addoff_kernel<<<nb, 256>>>(pOff, pCur, pBlk, batch, pCnt, n);
    fill_kernel<<<edge_grid, 256>>>(ei, pCur, pEsrc, ne, n);

    // per layer: gather (fp32 x for L0, bf16 h after) -> MLP
    for (int L = 0; L < 4; ++L) {
        gather_kernel<<<warp_grid, 256>>>(x, pH16, pOff, pEsrc, pB, n, (L > 0) ? 1 : 0);
        mlp_mma_kernel<<<mlp_grid, 256, MLP_SMEM>>>(
            pB, pW + (size_t)L * WL_BYTES, b1 + (size_t)L * DD, b2 + (size_t)L * DD,
            pH16, batch, pPool, n, (L < 3) ? 1 : 0);
    }

    float* out_pooled = pScratch;
    float* out_logits = pScratch + NGRAPH * DD;
    if (out_size >= NGRAPH * DD + NGRAPH * NCLASS) {
        out_pooled = out;
        out_logits = out + NGRAPH * DD;
    } else if (out_size == NGRAPH * NCLASS) {
        out_logits = out;
    } else if (out_size == NGRAPH * DD) {
        out_pooled = out;
    }
    finalize_kernel<<<NGRAPH, DD>>>(pPool, pCnt, wlin, blin, out_pooled, out_logits);
}

// round 14
// speedup vs baseline: 1.1042x; 1.0098x over previous
#include <cuda_runtime.h>
#include <cuda_bf16.h>
#include <cstdint>

#define DD 128
#define NODES_MAX 50000
#define NE_MAX 640000
#define NGRAPH 64
#define NCLASS 32
#define BM 128

// ---- smem layout for mma MLP (bytes from dynamic smem base) ----
#define SAB   272                    // bytes per bf16 row (136 elems) -> conflict-free ldmatrix
#define MATB  (128 * SAB)            // 34816 bytes per 128x128 bf16 matrix
#define SM_B1 0
#define SM_B2 512
#define SM_AH 1024
#define SM_AL (SM_AH + MATB)
#define SM_W  (SM_AL + MATB)         // [W1hi|W1lo|W2hi|W2lo]
#define MLP_SMEM (SM_W + 4 * MATB)   // 209920 bytes

#define WL_BYTES (4 * MATB)          // per-layer prepped weights

__device__ float g_bufB[NODES_MAX * DD];                 // fp32 aggregation buffer
__device__ __align__(16) unsigned short g_h16[NODES_MAX * DD];  // bf16 hidden state
__device__ float g_pool[NGRAPH * DD];
__device__ float g_cnt[NGRAPH];
__device__ float g_scratch[NGRAPH * DD + NGRAPH * NCLASS];
__device__ int   g_is64;
__device__ int   g_deg[NODES_MAX];
__device__ int   g_off[NODES_MAX + 1];
__device__ int   g_cur[NODES_MAX];
__device__ int   g_esrc[NE_MAX];
__device__ int   g_blk[256];
__device__ __align__(16) unsigned char g_wprep[4 * WL_BYTES];

// ================= helpers =================
__device__ __forceinline__ void red_add_v2(float* p, float x, float y) {
    asm volatile("red.global.add.v2.f32 [%0], {%1, %2};"
                 :: "l"(p), "f"(x), "f"(y) : "memory");
}
__device__ __forceinline__ uint32_t smem_u32(const void* p) {
    uint32_t a;
    asm("{ .reg .u64 t; cvta.to.shared.u64 t, %1; cvt.u32.u64 %0, t; }" : "=r"(a) : "l"(p));
    return a;
}
__device__ __forceinline__ unsigned short f2bf(float x) {
    return __bfloat16_as_ushort(__float2bfloat16_rn(x));
}
__device__ __forceinline__ float bf2f(unsigned short u) {
    return __bfloat162float(__ushort_as_bfloat16(u));
}
__device__ __forceinline__ void ldsm_x4(uint32_t* r, uint32_t addr) {
    asm volatile("ldmatrix.sync.aligned.m8n8.x4.shared.b16 {%0,%1,%2,%3}, [%4];"
                 : "=r"(r[0]), "=r"(r[1]), "=r"(r[2]), "=r"(r[3]) : "r"(addr));
}
__device__ __forceinline__ void mma_bf16(float* d, const uint32_t* a, const uint32_t* b) {
    asm volatile("mma.sync.aligned.m16n8k16.row.col.f32.bf16.bf16.f32 "
                 "{%0,%1,%2,%3}, {%4,%5,%6,%7}, {%8,%9}, {%0,%1,%2,%3};"
                 : "+f"(d[0]), "+f"(d[1]), "+f"(d[2]), "+f"(d[3])
                 : "r"(a[0]), "r"(a[1]), "r"(a[2]), "r"(a[3]), "r"(b[0]), "r"(b[1]));
}
// accumulate 8 bf16 (uint4) into float a[8]
__device__ __forceinline__ void acc8(float* a, uint4 u) {
    a[0] += bf2f((unsigned short)u.x); a[1] += bf2f((unsigned short)(u.x >> 16));
    a[2] += bf2f((unsigned short)u.y); a[3] += bf2f((unsigned short)(u.y >> 16));
    a[4] += bf2f((unsigned short)u.z); a[5] += bf2f((unsigned short)(u.z >> 16));
    a[6] += bf2f((unsigned short)u.w); a[7] += bf2f((unsigned short)(u.w >> 16));
}

// ---------- dtype detection: int64 viewed as int32 has odd words == 0 ----------
__global__ void detect_kernel(const int* __restrict__ idx32) {
    if (threadIdx.x == 0 && blockIdx.x == 0) {
        int is64 = 1;
        #pragma unroll 1
        for (int i = 1; i < 128; i += 2)
            if (idx32[i] != 0) { is64 = 0; break; }
        g_is64 = is64;
    }
}
__device__ __forceinline__ int load_idx(const void* p, int i, int is64) {
    if (is64) return (int)((const long long*)p)[i];
    return ((const int*)p)[i];
}

// ===== weight prep + zero deg/pool/cnt (one launch) =====
__global__ void wprep_kernel(const float* __restrict__ w1, const float* __restrict__ w2, int n) {
    int idx = blockIdx.x * blockDim.x + threadIdx.x;   // 131072 threads
    if (idx < n) g_deg[idx] = 0;
    if (idx < NGRAPH * DD) g_pool[idx] = 0.f;
    if (idx < NGRAPH) g_cnt[idx] = 0.f;
    if (idx >= 4 * 2 * DD * DD) return;
    int l = idx / (2 * DD * DD);
    int rem = idx % (2 * DD * DD);
    int m = rem / (DD * DD);
    int kn = rem % (DD * DD);
    int k = kn / DD, nn = kn % DD;
    const float* w = m ? w2 : w1;
    float v = w[(size_t)l * DD * DD + k * DD + nn];
    unsigned short hi = f2bf(v);
    unsigned short lo = f2bf(v - bf2f(hi));
    unsigned char* base = g_wprep + (size_t)l * WL_BYTES + (size_t)m * (2 * MATB);
    uint32_t a = (uint32_t)nn * SAB + (uint32_t)k * 2;
    *(unsigned short*)(base + a)        = hi;
    *(unsigned short*)(base + MATB + a) = lo;
}

// ================= CSR build =================
__global__ void hist_kernel(const void* __restrict__ ei, int* __restrict__ deg, int ne, int n) {
    int e = blockIdx.x * blockDim.x + threadIdx.x;
    if (e >= ne) return;
    const int is64 = g_is64;
    int s = load_idx(ei, e, is64);
    int d = load_idx(ei, ne + e, is64);
    if ((unsigned)s >= (unsigned)n || (unsigned)d >= (unsigned)n) return;
    atomicAdd(deg + d, 1);
}

// block-level exclusive scan (256/block), emit block totals
__global__ void blockscan_kernel(const int* __restrict__ deg, int* __restrict__ off,
                                 int* __restrict__ blk, int n) {
    __shared__ int ws[8];
    int i = blockIdx.x * 256 + threadIdx.x;
    int lane = threadIdx.x & 31, wd = threadIdx.x >> 5;
    int v = (i < n) ? deg[i] : 0;
    int x = v;
    #pragma unroll
    for (int d = 1; d < 32; d <<= 1) {
        int y = __shfl_up_sync(0xffffffffu, x, d);
        if (lane >= d) x += y;
    }
    if (lane == 31) ws[wd] = x;
    __syncthreads();
    if (wd == 0) {
        int s = (lane < 8) ? ws[lane] : 0;
        #pragma unroll
        for (int d = 1; d < 8; d <<= 1) {
            int y = __shfl_up_sync(0xffffffffu, s, d);
            if (lane >= d) s += y;
        }
        if (lane < 8) ws[lane] = s;
    }
    __syncthreads();
    int base = wd ? ws[wd - 1] : 0;
    if (i < n) off[i] = base + x - v;
    if (threadIdx.x == 255) blk[blockIdx.x] = ws[7];
}

// scan block totals (single block, 256 threads), write grand total to off[n]
__global__ void scan2_kernel(int* __restrict__ blk, int* __restrict__ off, int n, int nb) {
    __shared__ int ws[8];
    int t = threadIdx.x;
    int lane = t & 31, wd = t >> 5;
    int v = (t < nb) ? blk[t] : 0;
    int x = v;
    #pragma unroll
    for (int d = 1; d < 32; d <<= 1) {
        int y = __shfl_up_sync(0xffffffffu, x, d);
        if (lane >= d) x += y;
    }
    if (lane == 31) ws[wd] = x;
    __syncthreads();
    if (wd == 0) {
        int s = (lane < 8) ? ws[lane] : 0;
        #pragma unroll
        for (int d = 1; d < 8; d <<= 1) {
            int y = __shfl_up_sync(0xffffffffu, s, d);
            if (lane >= d) s += y;
        }
        if (lane < 8) ws[lane] = s;
    }
    __syncthreads();
    int base = wd ? ws[wd - 1] : 0;
    if (t < nb) blk[t] = base + x - v;     // exclusive block offset
    if (t == 255) off[n] = ws[7];          // grand total
}

// add block offsets, init cur, count graph sizes
__global__ void addoff_kernel(int* __restrict__ off, int* __restrict__ cur,
                              const int* __restrict__ blk, const void* __restrict__ batch,
                              float* __restrict__ cnt, int n) {
    int i = blockIdx.x * 256 + threadIdx.x;
    if (i >= n) return;
    int o = off[i] + blk[i >> 8];
    off[i] = o;
    cur[i] = o;
    int g = load_idx(batch, i, g_is64);
    if ((unsigned)g < (unsigned)NGRAPH) atomicAdd(cnt + g, 1.0f);
}

__global__ void fill_kernel(const void* __restrict__ ei, int* __restrict__ cur,
                            int* __restrict__ esrc, int ne, int n) {
    int e = blockIdx.x * blockDim.x + threadIdx.x;
    if (e >= ne) return;
    const int is64 = g_is64;
    int s = load_idx(ei, e, is64);
    int d = load_idx(ei, ne + e, is64);
    if ((unsigned)s >= (unsigned)n || (unsigned)d >= (unsigned)n) return;
    int pos = atomicAdd(cur + d, 1);
    esrc[pos] = s;
}

// ================= gather (layer 0, fp32 x): warp per node, float4 =================
__global__ void gather_f32_kernel(const float* __restrict__ h, const int* __restrict__ off,
                                  const int* __restrict__ esrc, float* __restrict__ out, int n) {
    int node = (blockIdx.x * blockDim.x + threadIdx.x) >> 5;
    int lane = threadIdx.x & 31;
    if (node >= n) return;
    int beg = off[node], end = off[node + 1];
    const size_t loff = (size_t)lane * 4;
    float4 a = *(const float4*)(h + (size_t)node * DD + loff);
    int e = beg;
    int m4 = beg + ((end - beg) & ~3);
    #pragma unroll 1
    for (; e < m4; e += 4) {
        int s0 = esrc[e], s1 = esrc[e + 1], s2 = esrc[e + 2], s3 = esrc[e + 3];
        float4 v0 = *(const float4*)(h + (size_t)s0 * DD + loff);
        float4 v1 = *(const float4*)(h + (size_t)s1 * DD + loff);
        float4 v2 = *(const float4*)(h + (size_t)s2 * DD + loff);
        float4 v3 = *(const float4*)(h + (size_t)s3 * DD + loff);
        a.x += v0.x + v1.x + v2.x + v3.x;
        a.y += v0.y + v1.y + v2.y + v3.y;
        a.z += v0.z + v1.z + v2.z + v3.z;
        a.w += v0.w + v1.w + v2.w + v3.w;
    }
    #pragma unroll 1
    for (; e < end; ++e) {
        int s = esrc[e];
        float4 v = *(const float4*)(h + (size_t)s * DD + loff);
        a.x += v.x; a.y += v.y; a.z += v.z; a.w += v.w;
    }
    *(float4*)(out + (size_t)node * DD + loff) = a;
}

// ================= gather (layers 1-3, bf16 h): HALF-WARP per node, uint4 loads =================
// 16 lanes/node, each lane covers 8 bf16 (16B) -> 16 LDG.128 per edge-row (half the instrs)
__global__ void gather_bf16_kernel(const unsigned short* __restrict__ h16,
                                   const int* __restrict__ off, const int* __restrict__ esrc,
                                   float* __restrict__ out, int n) {
    int idx = blockIdx.x * blockDim.x + threadIdx.x;
    int node = idx >> 4;
    int l = idx & 15;
    if (node >= n) return;
    int beg = off[node], end = off[node + 1];
    const size_t loff = (size_t)l * 8;
    float a[8];
    {
        uint4 u = *(const uint4*)(h16 + (size_t)node * DD + loff);
        a[0] = bf2f((unsigned short)u.x); a[1] = bf2f((unsigned short)(u.x >> 16));
        a[2] = bf2f((unsigned short)u.y); a[3] = bf2f((unsigned short)(u.y >> 16));
        a[4] = bf2f((unsigned short)u.z); a[5] = bf2f((unsigned short)(u.z >> 16));
        a[6] = bf2f((unsigned short)u.w); a[7] = bf2f((unsigned short)(u.w >> 16));
    }
    int e = beg;
    int m4 = beg + ((end - beg) & ~3);
    #pragma unroll 1
    for (; e < m4; e += 4) {
        int s0 = esrc[e], s1 = esrc[e + 1], s2 = esrc[e + 2], s3 = esrc[e + 3];
        uint4 u0 = *(const uint4*)(h16 + (size_t)s0 * DD + loff);
        uint4 u1 = *(const uint4*)(h16 + (size_t)s1 * DD + loff);
        uint4 u2 = *(const uint4*)(h16 + (size_t)s2 * DD + loff);
        uint4 u3 = *(const uint4*)(h16 + (size_t)s3 * DD + loff);
        acc8(a, u0); acc8(a, u1); acc8(a, u2); acc8(a, u3);
    }
    #pragma unroll 1
    for (; e < end; ++e) {
        uint4 u = *(const uint4*)(h16 + (size_t)esrc[e] * DD + loff);
        acc8(a, u);
    }
    float* op = out + (size_t)node * DD + loff;
    *(float4*)(op)     = make_float4(a[0], a[1], a[2], a[3]);
    *(float4*)(op + 4) = make_float4(a[4], a[5], a[6], a[7]);
}

// ================= MLP via mma.sync bf16 (3-term hi/lo split) =================
__device__ __forceinline__ void gemm_stage(uint32_t ah0, uint32_t al0,
                                           uint32_t bh_base, uint32_t bl_base,
                                           float acc[2][8][4]) {
    #pragma unroll 1
    for (int kk = 0; kk < 8; ++kk) {
        uint32_t ah[2][4], al[2][4];
        ldsm_x4(ah[0], ah0 + kk * 32);
        ldsm_x4(ah[1], ah0 + 16 * SAB + kk * 32);
        ldsm_x4(al[0], al0 + kk * 32);
        ldsm_x4(al[1], al0 + 16 * SAB + kk * 32);
        #pragma unroll
        for (int np = 0; np < 4; ++np) {
            uint32_t bh[4], bl[4];
            ldsm_x4(bh, bh_base + np * 16 * SAB + kk * 32);
            ldsm_x4(bl, bl_base + np * 16 * SAB + kk * 32);
            #pragma unroll
            for (int t = 0; t < 2; ++t) {
                #pragma unroll
                for (int mt = 0; mt < 2; ++mt) {
                    float* d = acc[mt][2 * np + t];
                    mma_bf16(d, ah[mt], &bh[2 * t]);
                    mma_bf16(d, ah[mt], &bl[2 * t]);
                    mma_bf16(d, al[mt], &bh[2 * t]);
                }
            }
        }
    }
}

// relu_out==1: write relu(h) as bf16 to out16.
// relu_out==0: LAST layer, red-add h into pool[batch[row]] (no h write).
__global__ void __launch_bounds__(256, 1)
mlp_mma_kernel(const float* __restrict__ in, const unsigned char* __restrict__ wprep,
               const float* __restrict__ b1, const float* __restrict__ b2,
               unsigned short* __restrict__ out16, const void* __restrict__ batch,
               float* __restrict__ pool, int n, int relu_out)
{
    extern __shared__ char smc[];
    const uint32_t sb = smem_u32(smc);

    const int tid = threadIdx.x;
    const int wid = tid >> 5;
    const int lane = tid & 31;
    const int rg = wid >> 1;          // warp row group (0..3): rows rg*32..+31
    const int cg = wid & 1;           // warp col group (0..1): cols cg*64..+63
    const int is64 = relu_out ? 0 : g_is64;
    const int row0 = blockIdx.x * BM;

    // ---- copy prepped weights for this layer (exact smem image) ----
    {
        const uint4* wsrc = (const uint4*)wprep;
        uint4* wdst = (uint4*)(smc + SM_W);
        #pragma unroll 8
        for (int i = tid; i < WL_BYTES / 16; i += 256) wdst[i] = wsrc[i];
    }
    // ---- biases ----
    if (tid < DD) {
        ((float*)(smc + SM_B1))[tid] = b1[tid];
        ((float*)(smc + SM_B2))[tid] = b2[tid];
    }
    // ---- load A tile (fp32 agg), split bf16 hi/lo ----
    {
        int r = tid >> 1;
        int c0 = (tid & 1) * 64;
        bool valid = (row0 + r) < n;
        const float* src = in + (size_t)(row0 + r) * DD + c0;
        char* ah = smc + SM_AH + r * SAB + c0 * 2;
        char* al = smc + SM_AL + r * SAB + c0 * 2;
        #pragma unroll
        for (int c = 0; c < 64; c += 4) {
            float4 v = valid ? *(const float4*)(src + c) : make_float4(0.f, 0.f, 0.f, 0.f);
            unsigned short h0 = f2bf(v.x), h1 = f2bf(v.y), h2 = f2bf(v.z), h3 = f2bf(v.w);
            unsigned short l0 = f2bf(v.x - bf2f(h0)), l1 = f2bf(v.y - bf2f(h1));
            unsigned short l2 = f2bf(v.z - bf2f(h2)), l3 = f2bf(v.w - bf2f(h3));
            *(uint2*)(ah + c * 2) = make_uint2((uint32_t)h0 | ((uint32_t)h1 << 16),
                                               (uint32_t)h2 | ((uint32_t)h3 << 16));
            *(uint2*)(al + c * 2) = make_uint2((uint32_t)l0 | ((uint32_t)l1 << 16),
                                               (uint32_t)l2 | ((uint32_t)l3 << 16));
        }
    }
    __syncthreads();

    // per-lane ldmatrix offsets
    const uint32_t a_off = (uint32_t)(rg * 32 + (lane & 15)) * SAB + ((lane >> 4) << 3) * 2;
    const uint32_t ah0 = sb + SM_AH + a_off;
    const uint32_t al0 = sb + SM_AL + a_off;
    {
        const int g = lane >> 3, ii = lane & 7;
        const uint32_t b_off = (uint32_t)(cg * 64 + ((g >> 1) << 3) + ii) * SAB + ((g & 1) << 3) * 2;

        float acc[2][8][4];

        // ======== stage 1: D1 = A @ W1 ========
        #pragma unroll
        for (int mt = 0; mt < 2; ++mt)
            #pragma unroll
            for (int nt = 0; nt < 8; ++nt)
                #pragma unroll
                for (int q = 0; q < 4; ++q) acc[mt][nt][q] = 0.f;

        gemm_stage(ah0, al0, sb + SM_W + b_off, sb + SM_W + MATB + b_off, acc);
        __syncthreads();   // all A reads done before overwrite

        // epilogue 1: z = relu(D1 + b1) -> bf16 hi/lo back into A
        {
            const float* sb1 = (const float*)(smc + SM_B1);
            const int qr = lane >> 2;
            const int qc = (lane & 3) * 2;
            #pragma unroll
            for (int mt = 0; mt < 2; ++mt) {
                #pragma unroll
                for (int nt = 0; nt < 8; ++nt) {
                    int row = rg * 32 + mt * 16 + qr;
                    int col = cg * 64 + nt * 8 + qc;
                    float bj0 = sb1[col], bj1 = sb1[col + 1];
                    float z0 = fmaxf(acc[mt][nt][0] + bj0, 0.f);
                    float z1 = fmaxf(acc[mt][nt][1] + bj1, 0.f);
                    float z2 = fmaxf(acc[mt][nt][2] + bj0, 0.f);
                    float z3 = fmaxf(acc[mt][nt][3] + bj1, 0.f);
                    unsigned short h0 = f2bf(z0), h1 = f2bf(z1), h2 = f2bf(z2), h3 = f2bf(z3);
                    unsigned short l0 = f2bf(z0 - bf2f(h0)), l1 = f2bf(z1 - bf2f(h1));
                    unsigned short l2 = f2bf(z2 - bf2f(h2)), l3 = f2bf(z3 - bf2f(h3));
                    uint32_t o0 = (uint32_t)row * SAB + (uint32_t)col * 2;
                    uint32_t o1 = (uint32_t)(row + 8) * SAB + (uint32_t)col * 2;
                    *(uint32_t*)(smc + SM_AH + o0) = (uint32_t)h0 | ((uint32_t)h1 << 16);
                    *(uint32_t*)(smc + SM_AH + o1) = (uint32_t)h2 | ((uint32_t)h3 << 16);
                    *(uint32_t*)(smc + SM_AL + o0) = (uint32_t)l0 | ((uint32_t)l1 << 16);
                    *(uint32_t*)(smc + SM_AL + o1) = (uint32_t)l2 | ((uint32_t)l3 << 16);
                }
            }
        }
        __syncthreads();

        // ======== stage 2: D2 = Z @ W2 ========
        #pragma unroll
        for (int mt = 0; mt < 2; ++mt)
            #pragma unroll
            for (int nt = 0; nt < 8; ++nt)
                #pragma unroll
                for (int q = 0; q < 4; ++q) acc[mt][nt][q] = 0.f;

        gemm_stage(ah0, al0, sb + SM_W + 2 * MATB + b_off, sb + SM_W + 3 * MATB + b_off, acc);

        // epilogue 2
        {
            const float* sb2 = (const float*)(smc + SM_B2);
            const int qr = lane >> 2;
            const int qc = (lane & 3) * 2;
            #pragma unroll
            for (int mt = 0; mt < 2; ++mt) {
                int row = rg * 32 + mt * 16 + qr;
                int grow0 = row0 + row;
                int grow1 = grow0 + 8;
                if (relu_out) {
                    #pragma unroll
                    for (int nt = 0; nt < 8; ++nt) {
                        int col = cg * 64 + nt * 8 + qc;
                        float bj0 = sb2[col], bj1 = sb2[col + 1];
                        float o0 = fmaxf(acc[mt][nt][0] + bj0, 0.f);
                        float o1 = fmaxf(acc[mt][nt][1] + bj1, 0.f);
                        float o2 = fmaxf(acc[mt][nt][2] + bj0, 0.f);
                        float o3 = fmaxf(acc[mt][nt][3] + bj1, 0.f);
                        if (grow0 < n)
                            *(uint32_t*)(out16 + (size_t)grow0 * DD + col) =
                                (uint32_t)f2bf(o0) | ((uint32_t)f2bf(o1) << 16);
                        if (grow1 < n)
                            *(uint32_t*)(out16 + (size_t)grow1 * DD + col) =
                                (uint32_t)f2bf(o2) | ((uint32_t)f2bf(o3) << 16);
                    }
                } else {
                    // last layer: accumulate straight into pool[batch[row]] (fp32, exact path)
                    int g0 = (grow0 < n) ? load_idx(batch, grow0, is64) : -1;
                    int g1 = (grow1 < n) ? load_idx(batch, grow1, is64) : -1;
                    bool v0 = (unsigned)g0 < (unsigned)NGRAPH;
                    bool v1 = (unsigned)g1 < (unsigned)NGRAPH;
                    #pragma unroll
                    for (int nt = 0; nt < 8; ++nt) {
                        int col = cg * 64 + nt * 8 + qc;
                        float bj0 = sb2[col], bj1 = sb2[col + 1];
                        if (v0) red_add_v2(pool + g0 * DD + col,
                                           acc[mt][nt][0] + bj0, acc[mt][nt][1] + bj1);
                        if (v1) red_add_v2(pool + g1 * DD + col,
                                           acc[mt][nt][2] + bj0, acc[mt][nt][3] + bj1);
                    }
                }
            }
        }
    }
}

// ---------- finalize: pooled mean + logits ----------
__global__ void finalize_kernel(const float* __restrict__ pool, const float* __restrict__ cnt,
                                const float* __restrict__ wlin, const float* __restrict__ blin,
                                float* __restrict__ out_pooled, float* __restrict__ out_logits) {
    __shared__ float ps[DD];
    int g = blockIdx.x;
    int t = threadIdx.x;
    float c = fmaxf(cnt[g], 1.0f);
    float v = pool[g * DD + t] / c;
    ps[t] = v;
    out_pooled[g * DD + t] = v;
    __syncthreads();
    if (t < NCLASS) {
        float s = blin[t];
        #pragma unroll 4
        for (int k = 0; k < DD; ++k) s += ps[k] * wlin[k * NCLASS + t];
        out_logits[g * NCLASS + t] = s;
    }
}

extern "C" void kernel_launch(void* const* d_in, const int* in_sizes, int n_in,
                              void* d_out, int out_size) {
    const float* x     = (const float*)d_in[0];
    const void*  ei    = d_in[1];
    const void*  batch = d_in[2];
    const float* w1    = (const float*)d_in[3];
    const float* b1    = (const float*)d_in[4];
    const float* w2    = (const float*)d_in[5];
    const float* b2    = (const float*)d_in[6];
    const float* wlin  = (const float*)d_in[7];
    const float* blin  = (const float*)d_in[8];
    float* out = (float*)d_out;

    int n  = in_sizes[0] / DD;
    int ne = in_sizes[1] / 2;
    if (n > NODES_MAX) n = NODES_MAX;
    if (ne > NE_MAX) ne = NE_MAX;

    float *pB, *pPool, *pCnt, *pScratch;
    unsigned short* pH16;
    int *pDeg, *pOff, *pCur, *pEsrc, *pBlk;
    unsigned char* pW;
    cudaGetSymbolAddress((void**)&pB, g_bufB);
    cudaGetSymbolAddress((void**)&pH16, g_h16);
    cudaGetSymbolAddress((void**)&pPool, g_pool);
    cudaGetSymbolAddress((void**)&pCnt, g_cnt);
    cudaGetSymbolAddress((void**)&pScratch, g_scratch);
    cudaGetSymbolAddress((void**)&pDeg, g_deg);
    cudaGetSymbolAddress((void**)&pOff, g_off);
    cudaGetSymbolAddress((void**)&pCur, g_cur);
    cudaGetSymbolAddress((void**)&pEsrc, g_esrc);
    cudaGetSymbolAddress((void**)&pBlk, g_blk);
    cudaGetSymbolAddress((void**)&pW, g_wprep);

    cudaFuncSetAttribute(mlp_mma_kernel, cudaFuncAttributeMaxDynamicSharedMemorySize, MLP_SMEM);

    const int mlp_grid   = (n + BM - 1) / BM;
    const int warp_grid  = (n * 32 + 255) / 256;
    const int hwarp_grid = (n * 16 + 255) / 256;
    const int edge_grid  = (ne + 255) / 256;
    const int nb         = (n + 255) / 256;

    detect_kernel<<<1, 32>>>((const int*)ei);
    wprep_kernel<<<512, 256>>>(w1, w2, n);   // also zeroes deg/pool/cnt

    // ---- CSR build (fast 3-kernel scan) ----
    hist_kernel<<<edge_grid, 256>>>(ei, pDeg, ne, n);
    blockscan_kernel<<<nb, 256>>>(pDeg, pOff, pBlk, n);
    scan2_kernel<<<1, 256>>>(pBlk, pOff, n, nb);
    addoff_kernel<<<nb, 256>>>(pOff, pCur, pBlk, batch, pCnt, n);
    fill_kernel<<<edge_grid, 256>>>(ei, pCur, pEsrc, ne, n);

    // per layer: gather (fp32 x for L0, bf16 h after) -> MLP
    for (int L = 0; L < 4; ++L) {
        if (L == 0)
            gather_f32_kernel<<<warp_grid, 256>>>(x, pOff, pEsrc, pB, n);
        else
            gather_bf16_kernel<<<hwarp_grid, 256>>>(pH16, pOff, pEsrc, pB, n);
        mlp_mma_kernel<<<mlp_grid, 256, MLP_SMEM>>>(
            pB, pW + (size_t)L * WL_BYTES, b1 + (size_t)L * DD, b2 + (size_t)L * DD,
            pH16, batch, pPool, n, (L < 3) ? 1 : 0);
    }

    float* out_pooled = pScratch;
    float* out_logits = pScratch + NGRAPH * DD;
    if (out_size >= NGRAPH * DD + NGRAPH * NCLASS) {
        out_pooled = out;
        out_logits = out + NGRAPH * DD;
    } else if (out_size == NGRAPH * NCLASS) {
        out_logits = out;
    } else if (out_size == NGRAPH * DD) {
        out_pooled = out;
    }
    finalize_kernel<<<NGRAPH, DD>>>(pPool, pCnt, wlin, blin, out_pooled, out_logits);
}

// round 15
// speedup vs baseline: 1.3420x; 1.2153x over previous
#include <cuda_runtime.h>
#include <cuda_bf16.h>
#include <cstdint>

#define DD 128
#define NODES_MAX 50000
#define NE_MAX 640000
#define NGRAPH 64
#define NCLASS 32
#define BM 128

// ---- smem layout for mma MLP (bytes from dynamic smem base) ----
#define SAB   272                    // bytes per bf16 row (136 elems) -> conflict-free ldmatrix
#define MATB  (128 * SAB)            // 34816 bytes per 128x128 bf16 matrix
#define SM_B1 0
#define SM_B2 512
#define SM_AH 1024                   // A: single bf16 matrix
#define SM_W  (SM_AH + MATB)         // [W1hi|W1lo|W2hi|W2lo]
#define MLP_SMEM (SM_W + 4 * MATB)   // 175104 bytes

#define WL_BYTES (4 * MATB)          // per-layer prepped weights

__device__ __align__(16) unsigned short g_agg16[NODES_MAX * DD];  // bf16 aggregation buffer
__device__ __align__(16) unsigned short g_h16[NODES_MAX * DD];    // bf16 hidden state
__device__ float g_pool[NGRAPH * DD];
__device__ float g_cnt[NGRAPH];
__device__ float g_scratch[NGRAPH * DD + NGRAPH * NCLASS];
__device__ int   g_is64;
__device__ int   g_deg[NODES_MAX];
__device__ int   g_off[NODES_MAX + 1];
__device__ int   g_cur[NODES_MAX];
__device__ int   g_esrc[NE_MAX];
__device__ int   g_blk[256];
__device__ __align__(16) unsigned char g_wprep[4 * WL_BYTES];

// ================= helpers =================
__device__ __forceinline__ void red_add_v2(float* p, float x, float y) {
    asm volatile("red.global.add.v2.f32 [%0], {%1, %2};"
                 :: "l"(p), "f"(x), "f"(y) : "memory");
}
__device__ __forceinline__ uint32_t smem_u32(const void* p) {
    uint32_t a;
    asm("{ .reg .u64 t; cvta.to.shared.u64 t, %1; cvt.u32.u64 %0, t; }" : "=r"(a) : "l"(p));
    return a;
}
__device__ __forceinline__ unsigned short f2bf(float x) {
    return __bfloat16_as_ushort(__float2bfloat16_rn(x));
}
__device__ __forceinline__ float bf2f(unsigned short u) {
    return __bfloat162float(__ushort_as_bfloat16(u));
}
__device__ __forceinline__ void ldsm_x4(uint32_t* r, uint32_t addr) {
    asm volatile("ldmatrix.sync.aligned.m8n8.x4.shared.b16 {%0,%1,%2,%3}, [%4];"
                 : "=r"(r[0]), "=r"(r[1]), "=r"(r[2]), "=r"(r[3]) : "r"(addr));
}
__device__ __forceinline__ void mma_bf16(float* d, const uint32_t* a, const uint32_t* b) {
    asm volatile("mma.sync.aligned.m16n8k16.row.col.f32.bf16.bf16.f32 "
                 "{%0,%1,%2,%3}, {%4,%5,%6,%7}, {%8,%9}, {%0,%1,%2,%3};"
                 : "+f"(d[0]), "+f"(d[1]), "+f"(d[2]), "+f"(d[3])
                 : "r"(a[0]), "r"(a[1]), "r"(a[2]), "r"(a[3]), "r"(b[0]), "r"(b[1]));
}
// accumulate 8 bf16 (uint4) into float a[8]
__device__ __forceinline__ void acc8(float* a, uint4 u) {
    a[0] += bf2f((unsigned short)u.x); a[1] += bf2f((unsigned short)(u.x >> 16));
    a[2] += bf2f((unsigned short)u.y); a[3] += bf2f((unsigned short)(u.y >> 16));
    a[4] += bf2f((unsigned short)u.z); a[5] += bf2f((unsigned short)(u.z >> 16));
    a[6] += bf2f((unsigned short)u.w); a[7] += bf2f((unsigned short)(u.w >> 16));
}
__device__ __forceinline__ uint4 pack8(const float* a) {
    return make_uint4((uint32_t)f2bf(a[0]) | ((uint32_t)f2bf(a[1]) << 16),
                      (uint32_t)f2bf(a[2]) | ((uint32_t)f2bf(a[3]) << 16),
                      (uint32_t)f2bf(a[4]) | ((uint32_t)f2bf(a[5]) << 16),
                      (uint32_t)f2bf(a[6]) | ((uint32_t)f2bf(a[7]) << 16));
}

// ---------- dtype detection: int64 viewed as int32 has odd words == 0 ----------
__global__ void detect_kernel(const int* __restrict__ idx32) {
    if (threadIdx.x == 0 && blockIdx.x == 0) {
        int is64 = 1;
        #pragma unroll 1
        for (int i = 1; i < 128; i += 2)
            if (idx32[i] != 0) { is64 = 0; break; }
        g_is64 = is64;
    }
}
__device__ __forceinline__ int load_idx(const void* p, int i, int is64) {
    if (is64) return (int)((const long long*)p)[i];
    return ((const int*)p)[i];
}

// ===== weight prep + zero deg/pool/cnt (one launch) =====
__global__ void wprep_kernel(const float* __restrict__ w1, const float* __restrict__ w2, int n) {
    int idx = blockIdx.x * blockDim.x + threadIdx.x;   // 131072 threads
    if (idx < n) g_deg[idx] = 0;
    if (idx < NGRAPH * DD) g_pool[idx] = 0.f;
    if (idx < NGRAPH) g_cnt[idx] = 0.f;
    if (idx >= 4 * 2 * DD * DD) return;
    int l = idx / (2 * DD * DD);
    int rem = idx % (2 * DD * DD);
    int m = rem / (DD * DD);
    int kn = rem % (DD * DD);
    int k = kn / DD, nn = kn % DD;
    const float* w = m ? w2 : w1;
    float v = w[(size_t)l * DD * DD + k * DD + nn];
    unsigned short hi = f2bf(v);
    unsigned short lo = f2bf(v - bf2f(hi));
    unsigned char* base = g_wprep + (size_t)l * WL_BYTES + (size_t)m * (2 * MATB);
    uint32_t a = (uint32_t)nn * SAB + (uint32_t)k * 2;
    *(unsigned short*)(base + a)        = hi;
    *(unsigned short*)(base + MATB + a) = lo;
}

// ================= CSR build =================
__global__ void hist_kernel(const void* __restrict__ ei, int* __restrict__ deg, int ne, int n) {
    int e = blockIdx.x * blockDim.x + threadIdx.x;
    if (e >= ne) return;
    const int is64 = g_is64;
    int s = load_idx(ei, e, is64);
    int d = load_idx(ei, ne + e, is64);
    if ((unsigned)s >= (unsigned)n || (unsigned)d >= (unsigned)n) return;
    atomicAdd(deg + d, 1);
}

// block-level exclusive scan (256/block), emit block totals
__global__ void blockscan_kernel(const int* __restrict__ deg, int* __restrict__ off,
                                 int* __restrict__ blk, int n) {
    __shared__ int ws[8];
    int i = blockIdx.x * 256 + threadIdx.x;
    int lane = threadIdx.x & 31, wd = threadIdx.x >> 5;
    int v = (i < n) ? deg[i] : 0;
    int x = v;
    #pragma unroll
    for (int d = 1; d < 32; d <<= 1) {
        int y = __shfl_up_sync(0xffffffffu, x, d);
        if (lane >= d) x += y;
    }
    if (lane == 31) ws[wd] = x;
    __syncthreads();
    if (wd == 0) {
        int s = (lane < 8) ? ws[lane] : 0;
        #pragma unroll
        for (int d = 1; d < 8; d <<= 1) {
            int y = __shfl_up_sync(0xffffffffu, s, d);
            if (lane >= d) s += y;
        }
        if (lane < 8) ws[lane] = s;
    }
    __syncthreads();
    int base = wd ? ws[wd - 1] : 0;
    if (i < n) off[i] = base + x - v;
    if (threadIdx.x == 255) blk[blockIdx.x] = ws[7];
}

// scan block totals (single block, 256 threads), write grand total to off[n]
__global__ void scan2_kernel(int* __restrict__ blk, int* __restrict__ off, int n, int nb) {
    __shared__ int ws[8];
    int t = threadIdx.x;
    int lane = t & 31, wd = t >> 5;
    int v = (t < nb) ? blk[t] : 0;
    int x = v;
    #pragma unroll
    for (int d = 1; d < 32; d <<= 1) {
        int y = __shfl_up_sync(0xffffffffu, x, d);
        if (lane >= d) x += y;
    }
    if (lane == 31) ws[wd] = x;
    __syncthreads();
    if (wd == 0) {
        int s = (lane < 8) ? ws[lane] : 0;
        #pragma unroll
        for (int d = 1; d < 8; d <<= 1) {
            int y = __shfl_up_sync(0xffffffffu, s, d);
            if (lane >= d) s += y;
        }
        if (lane < 8) ws[lane] = s;
    }
    __syncthreads();
    int base = wd ? ws[wd - 1] : 0;
    if (t < nb) blk[t] = base + x - v;     // exclusive block offset
    if (t == 255) off[n] = ws[7];          // grand total
}

// add block offsets, init cur, count graph sizes
__global__ void addoff_kernel(int* __restrict__ off, int* __restrict__ cur,
                              const int* __restrict__ blk, const void* __restrict__ batch,
                              float* __restrict__ cnt, int n) {
    int i = blockIdx.x * 256 + threadIdx.x;
    if (i >= n) return;
    int o = off[i] + blk[i >> 8];
    off[i] = o;
    cur[i] = o;
    int g = load_idx(batch, i, g_is64);
    if ((unsigned)g < (unsigned)NGRAPH) atomicAdd(cnt + g, 1.0f);
}

__global__ void fill_kernel(const void* __restrict__ ei, int* __restrict__ cur,
                            int* __restrict__ esrc, int ne, int n) {
    int e = blockIdx.x * blockDim.x + threadIdx.x;
    if (e >= ne) return;
    const int is64 = g_is64;
    int s = load_idx(ei, e, is64);
    int d = load_idx(ei, ne + e, is64);
    if ((unsigned)s >= (unsigned)n || (unsigned)d >= (unsigned)n) return;
    int pos = atomicAdd(cur + d, 1);
    esrc[pos] = s;
}

// ================= gather (layer 0, fp32 x): warp per node -> bf16 agg =================
__global__ void gather_f32_kernel(const float* __restrict__ h, const int* __restrict__ off,
                                  const int* __restrict__ esrc,
                                  unsigned short* __restrict__ out16, int n) {
    int node = (blockIdx.x * blockDim.x + threadIdx.x) >> 5;
    int lane = threadIdx.x & 31;
    if (node >= n) return;
    int beg = off[node], end = off[node + 1];
    const size_t loff = (size_t)lane * 4;
    float4 a = *(const float4*)(h + (size_t)node * DD + loff);
    int e = beg;
    int m4 = beg + ((end - beg) & ~3);
    #pragma unroll 1
    for (; e < m4; e += 4) {
        int s0 = esrc[e], s1 = esrc[e + 1], s2 = esrc[e + 2], s3 = esrc[e + 3];
        float4 v0 = *(const float4*)(h + (size_t)s0 * DD + loff);
        float4 v1 = *(const float4*)(h + (size_t)s1 * DD + loff);
        float4 v2 = *(const float4*)(h + (size_t)s2 * DD + loff);
        float4 v3 = *(const float4*)(h + (size_t)s3 * DD + loff);
        a.x += v0.x + v1.x + v2.x + v3.x;
        a.y += v0.y + v1.y + v2.y + v3.y;
        a.z += v0.z + v1.z + v2.z + v3.z;
        a.w += v0.w + v1.w + v2.w + v3.w;
    }
    #pragma unroll 1
    for (; e < end; ++e) {
        int s = esrc[e];
        float4 v = *(const float4*)(h + (size_t)s * DD + loff);
        a.x += v.x; a.y += v.y; a.z += v.z; a.w += v.w;
    }
    *(uint2*)(out16 + (size_t)node * DD + loff) =
        make_uint2((uint32_t)f2bf(a.x) | ((uint32_t)f2bf(a.y) << 16),
                   (uint32_t)f2bf(a.z) | ((uint32_t)f2bf(a.w) << 16));
}

// ================= gather (layers 1-3, bf16 h): HALF-WARP per node -> bf16 agg =================
__global__ void gather_bf16_kernel(const unsigned short* __restrict__ h16,
                                   const int* __restrict__ off, const int* __restrict__ esrc,
                                   unsigned short* __restrict__ out16, int n) {
    int idx = blockIdx.x * blockDim.x + threadIdx.x;
    int node = idx >> 4;
    int l = idx & 15;
    if (node >= n) return;
    int beg = off[node], end = off[node + 1];
    const size_t loff = (size_t)l * 8;
    float a[8];
    {
        uint4 u = *(const uint4*)(h16 + (size_t)node * DD + loff);
        a[0] = bf2f((unsigned short)u.x); a[1] = bf2f((unsigned short)(u.x >> 16));
        a[2] = bf2f((unsigned short)u.y); a[3] = bf2f((unsigned short)(u.y >> 16));
        a[4] = bf2f((unsigned short)u.z); a[5] = bf2f((unsigned short)(u.z >> 16));
        a[6] = bf2f((unsigned short)u.w); a[7] = bf2f((unsigned short)(u.w >> 16));
    }
    int e = beg;
    int m4 = beg + ((end - beg) & ~3);
    #pragma unroll 1
    for (; e < m4; e += 4) {
        int s0 = esrc[e], s1 = esrc[e + 1], s2 = esrc[e + 2], s3 = esrc[e + 3];
        uint4 u0 = *(const uint4*)(h16 + (size_t)s0 * DD + loff);
        uint4 u1 = *(const uint4*)(h16 + (size_t)s1 * DD + loff);
        uint4 u2 = *(const uint4*)(h16 + (size_t)s2 * DD + loff);
        uint4 u3 = *(const uint4*)(h16 + (size_t)s3 * DD + loff);
        acc8(a, u0); acc8(a, u1); acc8(a, u2); acc8(a, u3);
    }
    #pragma unroll 1
    for (; e < end; ++e) {
        uint4 u = *(const uint4*)(h16 + (size_t)esrc[e] * DD + loff);
        acc8(a, u);
    }
    *(uint4*)(out16 + (size_t)node * DD + loff) = pack8(a);
}

// ================= MLP via mma.sync bf16 (A: bf16; W: 2-term hi/lo) =================
__device__ __forceinline__ void gemm_stage(uint32_t ah0,
                                           uint32_t bh_base, uint32_t bl_base,
                                           float acc[2][8][4]) {
    #pragma unroll 1
    for (int kk = 0; kk < 8; ++kk) {
        uint32_t ah[2][4];
        ldsm_x4(ah[0], ah0 + kk * 32);
        ldsm_x4(ah[1], ah0 + 16 * SAB + kk * 32);
        #pragma unroll
        for (int np = 0; np < 4; ++np) {
            uint32_t bh[4], bl[4];
            ldsm_x4(bh, bh_base + np * 16 * SAB + kk * 32);
            ldsm_x4(bl, bl_base + np * 16 * SAB + kk * 32);
            #pragma unroll
            for (int t = 0; t < 2; ++t) {
                #pragma unroll
                for (int mt = 0; mt < 2; ++mt) {
                    float* d = acc[mt][2 * np + t];
                    mma_bf16(d, ah[mt], &bh[2 * t]);
                    mma_bf16(d, ah[mt], &bl[2 * t]);
                }
            }
        }
    }
}

// relu_out==1: write relu(h) as bf16 to out16.
// relu_out==0: LAST layer, red-add h into pool[batch[row]] (no h write).
__global__ void __launch_bounds__(256, 1)
mlp_mma_kernel(const unsigned short* __restrict__ in16, const unsigned char* __restrict__ wprep,
               const float* __restrict__ b1, const float* __restrict__ b2,
               unsigned short* __restrict__ out16, const void* __restrict__ batch,
               float* __restrict__ pool, int n, int relu_out)
{
    extern __shared__ char smc[];
    const uint32_t sb = smem_u32(smc);

    const int tid = threadIdx.x;
    const int wid = tid >> 5;
    const int lane = tid & 31;
    const int rg = wid >> 1;          // warp row group (0..3): rows rg*32..+31
    const int cg = wid & 1;           // warp col group (0..1): cols cg*64..+63
    const int is64 = relu_out ? 0 : g_is64;
    const int row0 = blockIdx.x * BM;

    // ---- copy prepped weights for this layer (exact smem image) ----
    {
        const uint4* wsrc = (const uint4*)wprep;
        uint4* wdst = (uint4*)(smc + SM_W);
        #pragma unroll 8
        for (int i = tid; i < WL_BYTES / 16; i += 256) wdst[i] = wsrc[i];
    }
    // ---- biases ----
    if (tid < DD) {
        ((float*)(smc + SM_B1))[tid] = b1[tid];
        ((float*)(smc + SM_B2))[tid] = b2[tid];
    }
    // ---- load A tile (bf16 agg, straight copy) ----
    {
        int r = tid >> 1;
        int c0 = (tid & 1) * 64;
        bool valid = (row0 + r) < n;
        const unsigned short* src = in16 + (size_t)(row0 + r) * DD + c0;
        char* ah = smc + SM_AH + r * SAB + c0 * 2;
        #pragma unroll
        for (int c = 0; c < 64; c += 8) {
            uint4 v = valid ? *(const uint4*)(src + c) : make_uint4(0u, 0u, 0u, 0u);
            *(uint4*)(ah + c * 2) = v;
        }
    }
    __syncthreads();

    // per-lane ldmatrix offsets
    const uint32_t a_off = (uint32_t)(rg * 32 + (lane & 15)) * SAB + ((lane >> 4) << 3) * 2;
    const uint32_t ah0 = sb + SM_AH + a_off;
    {
        const int g = lane >> 3, ii = lane & 7;
        const uint32_t b_off = (uint32_t)(cg * 64 + ((g >> 1) << 3) + ii) * SAB + ((g & 1) << 3) * 2;

        float acc[2][8][4];

        // ======== stage 1: D1 = A @ W1 ========
        #pragma unroll
        for (int mt = 0; mt < 2; ++mt)
            #pragma unroll
            for (int nt = 0; nt < 8; ++nt)
                #pragma unroll
                for (int q = 0; q < 4; ++q) acc[mt][nt][q] = 0.f;

        gemm_stage(ah0, sb + SM_W + b_off, sb + SM_W + MATB + b_off, acc);
        __syncthreads();   // all A reads done before overwrite

        // epilogue 1: z = relu(D1 + b1) -> bf16 back into A
        {
            const float* sb1 = (const float*)(smc + SM_B1);
            const int qr = lane >> 2;
            const int qc = (lane & 3) * 2;
            #pragma unroll
            for (int mt = 0; mt < 2; ++mt) {
                #pragma unroll
                for (int nt = 0; nt < 8; ++nt) {
                    int row = rg * 32 + mt * 16 + qr;
                    int col = cg * 64 + nt * 8 + qc;
                    float bj0 = sb1[col], bj1 = sb1[col + 1];
                    float z0 = fmaxf(acc[mt][nt][0] + bj0, 0.f);
                    float z1 = fmaxf(acc[mt][nt][1] + bj1, 0.f);
                    float z2 = fmaxf(acc[mt][nt][2] + bj0, 0.f);
                    float z3 = fmaxf(acc[mt][nt][3] + bj1, 0.f);
                    uint32_t o0 = (uint32_t)row * SAB + (uint32_t)col * 2;
                    uint32_t o1 = (uint32_t)(row + 8) * SAB + (uint32_t)col * 2;
                    *(uint32_t*)(smc + SM_AH + o0) = (uint32_t)f2bf(z0) | ((uint32_t)f2bf(z1) << 16);
                    *(uint32_t*)(smc + SM_AH + o1) = (uint32_t)f2bf(z2) | ((uint32_t)f2bf(z3) << 16);
                }
            }
        }
        __syncthreads();

        // ======== stage 2: D2 = Z @ W2 ========
        #pragma unroll
        for (int mt = 0; mt < 2; ++mt)
            #pragma unroll
            for (int nt = 0; nt < 8; ++nt)
                #pragma unroll
                for (int q = 0; q < 4; ++q) acc[mt][nt][q] = 0.f;

        gemm_stage(ah0, sb + SM_W + 2 * MATB + b_off, sb + SM_W + 3 * MATB + b_off, acc);

        // epilogue 2
        {
            const float* sb2 = (const float*)(smc + SM_B2);
            const int qr = lane >> 2;
            const int qc = (lane & 3) * 2;
            #pragma unroll
            for (int mt = 0; mt < 2; ++mt) {
                int row = rg * 32 + mt * 16 + qr;
                int grow0 = row0 + row;
                int grow1 = grow0 + 8;
                if (relu_out) {
                    #pragma unroll
                    for (int nt = 0; nt < 8; ++nt) {
                        int col = cg * 64 + nt * 8 + qc;
                        float bj0 = sb2[col], bj1 = sb2[col + 1];
                        float o0 = fmaxf(acc[mt][nt][0] + bj0, 0.f);
                        float o1 = fmaxf(acc[mt][nt][1] + bj1, 0.f);
                        float o2 = fmaxf(acc[mt][nt][2] + bj0, 0.f);
                        float o3 = fmaxf(acc[mt][nt][3] + bj1, 0.f);
                        if (grow0 < n)
                            *(uint32_t*)(out16 + (size_t)grow0 * DD + col) =
                                (uint32_t)f2bf(o0) | ((uint32_t)f2bf(o1) << 16);
                        if (grow1 < n)
                            *(uint32_t*)(out16 + (size_t)grow1 * DD + col) =
                                (uint32_t)f2bf(o2) | ((uint32_t)f2bf(o3) << 16);
                    }
                } else {
                    // last layer: accumulate straight into pool[batch[row]] (fp32, exact path)
                    int g0 = (grow0 < n) ? load_idx(batch, grow0, is64) : -1;
                    int g1 = (grow1 < n) ? load_idx(batch, grow1, is64) : -1;
                    bool v0 = (unsigned)g0 < (unsigned)NGRAPH;
                    bool v1 = (unsigned)g1 < (unsigned)NGRAPH;
                    #pragma unroll
                    for (int nt = 0; nt < 8; ++nt) {
                        int col = cg * 64 + nt * 8 + qc;
                        float bj0 = sb2[col], bj1 = sb2[col + 1];
                        if (v0) red_add_v2(pool + g0 * DD + col,
                                           acc[mt][nt][0] + bj0, acc[mt][nt][1] + bj1);
                        if (v1) red_add_v2(pool + g1 * DD + col,
                                           acc[mt][nt][2] + bj0, acc[mt][nt][3] + bj1);
                    }
                }
            }
        }
    }
}

// ---------- finalize: pooled mean + logits ----------
__global__ void finalize_kernel(const float* __restrict__ pool, const float* __restrict__ cnt,
                                const float* __restrict__ wlin, const float* __restrict__ blin,
                                float* __restrict__ out_pooled, float* __restrict__ out_logits) {
    __shared__ float ps[DD];
    int g = blockIdx.x;
    int t = threadIdx.x;
    float c = fmaxf(cnt[g], 1.0f);
    float v = pool[g * DD + t] / c;
    ps[t] = v;
    out_pooled[g * DD + t] = v;
    __syncthreads();
    if (t < NCLASS) {
        float s = blin[t];
        #pragma unroll 4
        for (int k = 0; k < DD; ++k) s += ps[k] * wlin[k * NCLASS + t];
        out_logits[g * NCLASS + t] = s;
    }
}

extern "C" void kernel_launch(void* const* d_in, const int* in_sizes, int n_in,
                              void* d_out, int out_size) {
    const float* x     = (const float*)d_in[0];
    const void*  ei    = d_in[1];
    const void*  batch = d_in[2];
    const float* w1    = (const float*)d_in[3];
    const float* b1    = (const float*)d_in[4];
    const float* w2    = (const float*)d_in[5];
    const float* b2    = (const float*)d_in[6];
    const float* wlin  = (const float*)d_in[7];
    const float* blin  = (const float*)d_in[8];
    float* out = (float*)d_out;

    int n  = in_sizes[0] / DD;
    int ne = in_sizes[1] / 2;
    if (n > NODES_MAX) n = NODES_MAX;
    if (ne > NE_MAX) ne = NE_MAX;

    float *pPool, *pCnt, *pScratch;
    unsigned short *pH16, *pAgg16;
    int *pDeg, *pOff, *pCur, *pEsrc, *pBlk;
    unsigned char* pW;
    cudaGetSymbolAddress((void**)&pAgg16, g_agg16);
    cudaGetSymbolAddress((void**)&pH16, g_h16);
    cudaGetSymbolAddress((void**)&pPool, g_pool);
    cudaGetSymbolAddress((void**)&pCnt, g_cnt);
    cudaGetSymbolAddress((void**)&pScratch, g_scratch);
    cudaGetSymbolAddress((void**)&pDeg, g_deg);
    cudaGetSymbolAddress((void**)&pOff, g_off);
    cudaGetSymbolAddress((void**)&pCur, g_cur);
    cudaGetSymbolAddress((void**)&pEsrc, g_esrc);
    cudaGetSymbolAddress((void**)&pBlk, g_blk);
    cudaGetSymbolAddress((void**)&pW, g_wprep);

    cudaFuncSetAttribute(mlp_mma_kernel, cudaFuncAttributeMaxDynamicSharedMemorySize, MLP_SMEM);

    const int mlp_grid   = (n + BM - 1) / BM;
    const int warp_grid  = (n * 32 + 255) / 256;
    const int hwarp_grid = (n * 16 + 255) / 256;
    const int edge_grid  = (ne + 255) / 256;
    const int nb         = (n + 255) / 256;

    detect_kernel<<<1, 32>>>((const int*)ei);
    wprep_kernel<<<512, 256>>>(w1, w2, n);   // also zeroes deg/pool/cnt

    // ---- CSR build (fast 3-kernel scan) ----
    hist_kernel<<<edge_grid, 256>>>(ei, pDeg, ne, n);
    blockscan_kernel<<<nb, 256>>>(pDeg, pOff, pBlk, n);
    scan2_kernel<<<1, 256>>>(pBlk, pOff, n, nb);
    addoff_kernel<<<nb, 256>>>(pOff, pCur, pBlk, batch, pCnt, n);
    fill_kernel<<<edge_grid, 256>>>(ei, pCur, pEsrc, ne, n);

    // per layer: gather (fp32 x for L0, bf16 h after) -> bf16 agg -> MLP
    for (int L = 0; L < 4; ++L) {
        if (L == 0)
            gather_f32_kernel<<<warp_grid, 256>>>(x, pOff, pEsrc, pAgg16, n);
        else
            gather_bf16_kernel<<<hwarp_grid, 256>>>(pH16, pOff, pEsrc, pAgg16, n);
        mlp_mma_kernel<<<mlp_grid, 256, MLP_SMEM>>>(
            pAgg16, pW + (size_t)L * WL_BYTES, b1 + (size_t)L * DD, b2 + (size_t)L * DD,
            pH16, batch, pPool, n, (L < 3) ? 1 : 0);
    }

    float* out_pooled = pScratch;
    float* out_logits = pScratch + NGRAPH * DD;
    if (out_size >= NGRAPH * DD + NGRAPH * NCLASS) {
        out_pooled = out;
        out_logits = out + NGRAPH * DD;
    } else if (out_size == NGRAPH * NCLASS) {
        out_logits = out;
    } else if (out_size == NGRAPH * DD) {
        out_pooled = out;
    }
    finalize_kernel<<<NGRAPH, DD>>>(pPool, pCnt, wlin, blin, out_pooled, out_logits);
}

// round 16
// speedup vs baseline: 1.4072x; 1.0486x over previous
#include <cuda_runtime.h>
#include <cuda_bf16.h>
#include <cstdint>

#define DD 128
#define NODES_MAX 50000
#define NE_MAX 640000
#define NGRAPH 64
#define NCLASS 32
#define BM 128
#define MLP_GRID 152

// ---- smem layout for mma MLP (bytes from dynamic smem base) ----
#define SAB   272                    // bytes per bf16 row (136 elems) -> conflict-free ldmatrix
#define MATB  (128 * SAB)            // 34816 bytes per 128x128 bf16 matrix
#define SM_B1 0
#define SM_B2 512
#define SM_AH 1024                   // A: single bf16 matrix
#define SM_W  (SM_AH + MATB)         // [W1hi|W1lo|W2hi|W2lo]
#define MLP_SMEM (SM_W + 4 * MATB)   // 175104 bytes

#define WL_BYTES (4 * MATB)          // per-layer prepped weights

__device__ __align__(16) unsigned short g_x16[NODES_MAX * DD];    // bf16 input features
__device__ __align__(16) unsigned short g_agg16[NODES_MAX * DD];  // bf16 aggregation buffer
__device__ __align__(16) unsigned short g_h16[NODES_MAX * DD];    // bf16 hidden state
__device__ float g_pool[NGRAPH * DD];
__device__ float g_cnt[NGRAPH];
__device__ float g_scratch[NGRAPH * DD + NGRAPH * NCLASS];
__device__ int   g_is64;
__device__ int   g_deg[NODES_MAX];
__device__ int   g_off[NODES_MAX + 1];
__device__ int   g_cur[NODES_MAX];
__device__ int   g_esrc[NE_MAX];
__device__ int   g_blk[256];
__device__ __align__(16) unsigned char g_wprep[4 * WL_BYTES];

// ================= helpers =================
__device__ __forceinline__ void red_add_v2(float* p, float x, float y) {
    asm volatile("red.global.add.v2.f32 [%0], {%1, %2};"
                 :: "l"(p), "f"(x), "f"(y) : "memory");
}
__device__ __forceinline__ uint32_t smem_u32(const void* p) {
    uint32_t a;
    asm("{ .reg .u64 t; cvta.to.shared.u64 t, %1; cvt.u32.u64 %0, t; }" : "=r"(a) : "l"(p));
    return a;
}
__device__ __forceinline__ unsigned short f2bf(float x) {
    return __bfloat16_as_ushort(__float2bfloat16_rn(x));
}
__device__ __forceinline__ float bf2f(unsigned short u) {
    return __bfloat162float(__ushort_as_bfloat16(u));
}
__device__ __forceinline__ void ldsm_x4(uint32_t* r, uint32_t addr) {
    asm volatile("ldmatrix.sync.aligned.m8n8.x4.shared.b16 {%0,%1,%2,%3}, [%4];"
                 : "=r"(r[0]), "=r"(r[1]), "=r"(r[2]), "=r"(r[3]) : "r"(addr));
}
__device__ __forceinline__ void mma_bf16(float* d, const uint32_t* a, const uint32_t* b) {
    asm volatile("mma.sync.aligned.m16n8k16.row.col.f32.bf16.bf16.f32 "
                 "{%0,%1,%2,%3}, {%4,%5,%6,%7}, {%8,%9}, {%0,%1,%2,%3};"
                 : "+f"(d[0]), "+f"(d[1]), "+f"(d[2]), "+f"(d[3])
                 : "r"(a[0]), "r"(a[1]), "r"(a[2]), "r"(a[3]), "r"(b[0]), "r"(b[1]));
}
// accumulate 8 bf16 (uint4) into float a[8]
__device__ __forceinline__ void acc8(float* a, uint4 u) {
    a[0] += bf2f((unsigned short)u.x); a[1] += bf2f((unsigned short)(u.x >> 16));
    a[2] += bf2f((unsigned short)u.y); a[3] += bf2f((unsigned short)(u.y >> 16));
    a[4] += bf2f((unsigned short)u.z); a[5] += bf2f((unsigned short)(u.z >> 16));
    a[6] += bf2f((unsigned short)u.w); a[7] += bf2f((unsigned short)(u.w >> 16));
}
__device__ __forceinline__ uint4 pack8(const float* a) {
    return make_uint4((uint32_t)f2bf(a[0]) | ((uint32_t)f2bf(a[1]) << 16),
                      (uint32_t)f2bf(a[2]) | ((uint32_t)f2bf(a[3]) << 16),
                      (uint32_t)f2bf(a[4]) | ((uint32_t)f2bf(a[5]) << 16),
                      (uint32_t)f2bf(a[6]) | ((uint32_t)f2bf(a[7]) << 16));
}

// ---------- dtype detection: int64 viewed as int32 has odd words == 0 ----------
__global__ void detect_kernel(const int* __restrict__ idx32) {
    if (threadIdx.x == 0 && blockIdx.x == 0) {
        int is64 = 1;
        #pragma unroll 1
        for (int i = 1; i < 128; i += 2)
            if (idx32[i] != 0) { is64 = 0; break; }
        g_is64 = is64;
    }
}
__device__ __forceinline__ int load_idx(const void* p, int i, int is64) {
    if (is64) return (int)((const long long*)p)[i];
    return ((const int*)p)[i];
}

// ===== x fp32 -> bf16 (one-time) =====
__global__ void xconv_kernel(const float* __restrict__ x, unsigned short* __restrict__ x16, int n4) {
    int i = blockIdx.x * blockDim.x + threadIdx.x;
    if (i >= n4) return;
    float4 v = ((const float4*)x)[i];
    ((uint2*)x16)[i] = make_uint2((uint32_t)f2bf(v.x) | ((uint32_t)f2bf(v.y) << 16),
                                  (uint32_t)f2bf(v.z) | ((uint32_t)f2bf(v.w) << 16));
}

// ===== weight prep + zero deg/pool/cnt (one launch) =====
__global__ void wprep_kernel(const float* __restrict__ w1, const float* __restrict__ w2, int n) {
    int idx = blockIdx.x * blockDim.x + threadIdx.x;   // 131072 threads
    if (idx < n) g_deg[idx] = 0;
    if (idx < NGRAPH * DD) g_pool[idx] = 0.f;
    if (idx < NGRAPH) g_cnt[idx] = 0.f;
    if (idx >= 4 * 2 * DD * DD) return;
    int l = idx / (2 * DD * DD);
    int rem = idx % (2 * DD * DD);
    int m = rem / (DD * DD);
    int kn = rem % (DD * DD);
    int k = kn / DD, nn = kn % DD;
    const float* w = m ? w2 : w1;
    float v = w[(size_t)l * DD * DD + k * DD + nn];
    unsigned short hi = f2bf(v);
    unsigned short lo = f2bf(v - bf2f(hi));
    unsigned char* base = g_wprep + (size_t)l * WL_BYTES + (size_t)m * (2 * MATB);
    uint32_t a = (uint32_t)nn * SAB + (uint32_t)k * 2;
    *(unsigned short*)(base + a)        = hi;
    *(unsigned short*)(base + MATB + a) = lo;
}

// ================= CSR build =================
__global__ void hist_kernel(const void* __restrict__ ei, int* __restrict__ deg, int ne, int n) {
    int e = blockIdx.x * blockDim.x + threadIdx.x;
    if (e >= ne) return;
    const int is64 = g_is64;
    int s = load_idx(ei, e, is64);
    int d = load_idx(ei, ne + e, is64);
    if ((unsigned)s >= (unsigned)n || (unsigned)d >= (unsigned)n) return;
    atomicAdd(deg + d, 1);
}

// block-level exclusive scan (256/block), emit block totals
__global__ void blockscan_kernel(const int* __restrict__ deg, int* __restrict__ off,
                                 int* __restrict__ blk, int n) {
    __shared__ int ws[8];
    int i = blockIdx.x * 256 + threadIdx.x;
    int lane = threadIdx.x & 31, wd = threadIdx.x >> 5;
    int v = (i < n) ? deg[i] : 0;
    int x = v;
    #pragma unroll
    for (int d = 1; d < 32; d <<= 1) {
        int y = __shfl_up_sync(0xffffffffu, x, d);
        if (lane >= d) x += y;
    }
    if (lane == 31) ws[wd] = x;
    __syncthreads();
    if (wd == 0) {
        int s = (lane < 8) ? ws[lane] : 0;
        #pragma unroll
        for (int d = 1; d < 8; d <<= 1) {
            int y = __shfl_up_sync(0xffffffffu, s, d);
            if (lane >= d) s += y;
        }
        if (lane < 8) ws[lane] = s;
    }
    __syncthreads();
    int base = wd ? ws[wd - 1] : 0;
    if (i < n) off[i] = base + x - v;
    if (threadIdx.x == 255) blk[blockIdx.x] = ws[7];
}

// scan block totals (single block, 256 threads), write grand total to off[n]
__global__ void scan2_kernel(int* __restrict__ blk, int* __restrict__ off, int n, int nb) {
    __shared__ int ws[8];
    int t = threadIdx.x;
    int lane = t & 31, wd = t >> 5;
    int v = (t < nb) ? blk[t] : 0;
    int x = v;
    #pragma unroll
    for (int d = 1; d < 32; d <<= 1) {
        int y = __shfl_up_sync(0xffffffffu, x, d);
        if (lane >= d) x += y;
    }
    if (lane == 31) ws[wd] = x;
    __syncthreads();
    if (wd == 0) {
        int s = (lane < 8) ? ws[lane] : 0;
        #pragma unroll
        for (int d = 1; d < 8; d <<= 1) {
            int y = __shfl_up_sync(0xffffffffu, s, d);
            if (lane >= d) s += y;
        }
        if (lane < 8) ws[lane] = s;
    }
    __syncthreads();
    int base = wd ? ws[wd - 1] : 0;
    if (t < nb) blk[t] = base + x - v;     // exclusive block offset
    if (t == 255) off[n] = ws[7];          // grand total
}

// add block offsets, init cur, count graph sizes
__global__ void addoff_kernel(int* __restrict__ off, int* __restrict__ cur,
                              const int* __restrict__ blk, const void* __restrict__ batch,
                              float* __restrict__ cnt, int n) {
    int i = blockIdx.x * 256 + threadIdx.x;
    if (i >= n) return;
    int o = off[i] + blk[i >> 8];
    off[i] = o;
    cur[i] = o;
    int g = load_idx(batch, i, g_is64);
    if ((unsigned)g < (unsigned)NGRAPH) atomicAdd(cnt + g, 1.0f);
}

__global__ void fill_kernel(const void* __restrict__ ei, int* __restrict__ cur,
                            int* __restrict__ esrc, int ne, int n) {
    int e = blockIdx.x * blockDim.x + threadIdx.x;
    if (e >= ne) return;
    const int is64 = g_is64;
    int s = load_idx(ei, e, is64);
    int d = load_idx(ei, ne + e, is64);
    if ((unsigned)s >= (unsigned)n || (unsigned)d >= (unsigned)n) return;
    int pos = atomicAdd(cur + d, 1);
    esrc[pos] = s;
}

// ================= gather (bf16 h): HALF-WARP per node -> bf16 agg =================
__global__ void gather_bf16_kernel(const unsigned short* __restrict__ h16,
                                   const int* __restrict__ off, const int* __restrict__ esrc,
                                   unsigned short* __restrict__ out16, int n) {
    int idx = blockIdx.x * blockDim.x + threadIdx.x;
    int node = idx >> 4;
    int l = idx & 15;
    if (node >= n) return;
    int beg = off[node], end = off[node + 1];
    const size_t loff = (size_t)l * 8;
    float a[8];
    {
        uint4 u = *(const uint4*)(h16 + (size_t)node * DD + loff);
        a[0] = bf2f((unsigned short)u.x); a[1] = bf2f((unsigned short)(u.x >> 16));
        a[2] = bf2f((unsigned short)u.y); a[3] = bf2f((unsigned short)(u.y >> 16));
        a[4] = bf2f((unsigned short)u.z); a[5] = bf2f((unsigned short)(u.z >> 16));
        a[6] = bf2f((unsigned short)u.w); a[7] = bf2f((unsigned short)(u.w >> 16));
    }
    int e = beg;
    int m4 = beg + ((end - beg) & ~3);
    #pragma unroll 1
    for (; e < m4; e += 4) {
        int s0 = esrc[e], s1 = esrc[e + 1], s2 = esrc[e + 2], s3 = esrc[e + 3];
        uint4 u0 = *(const uint4*)(h16 + (size_t)s0 * DD + loff);
        uint4 u1 = *(const uint4*)(h16 + (size_t)s1 * DD + loff);
        uint4 u2 = *(const uint4*)(h16 + (size_t)s2 * DD + loff);
        uint4 u3 = *(const uint4*)(h16 + (size_t)s3 * DD + loff);
        acc8(a, u0); acc8(a, u1); acc8(a, u2); acc8(a, u3);
    }
    #pragma unroll 1
    for (; e < end; ++e) {
        uint4 u = *(const uint4*)(h16 + (size_t)esrc[e] * DD + loff);
        acc8(a, u);
    }
    *(uint4*)(out16 + (size_t)node * DD + loff) = pack8(a);
}

// ================= MLP via mma.sync bf16 (A: bf16; W: 2-term hi/lo), PERSISTENT =================
__device__ __forceinline__ void gemm_stage(uint32_t ah0,
                                           uint32_t bh_base, uint32_t bl_base,
                                           float acc[2][8][4]) {
    #pragma unroll 1
    for (int kk = 0; kk < 8; ++kk) {
        uint32_t ah[2][4];
        ldsm_x4(ah[0], ah0 + kk * 32);
        ldsm_x4(ah[1], ah0 + 16 * SAB + kk * 32);
        #pragma unroll
        for (int np = 0; np < 4; ++np) {
            uint32_t bh[4], bl[4];
            ldsm_x4(bh, bh_base + np * 16 * SAB + kk * 32);
            ldsm_x4(bl, bl_base + np * 16 * SAB + kk * 32);
            #pragma unroll
            for (int t = 0; t < 2; ++t) {
                #pragma unroll
                for (int mt = 0; mt < 2; ++mt) {
                    float* d = acc[mt][2 * np + t];
                    mma_bf16(d, ah[mt], &bh[2 * t]);
                    mma_bf16(d, ah[mt], &bl[2 * t]);
                }
            }
        }
    }
}

// relu_out==1: write relu(h) as bf16 to out16.
// relu_out==0: LAST layer, red-add h into pool[batch[row]] (no h write).
__global__ void __launch_bounds__(256, 1)
mlp_mma_kernel(const unsigned short* __restrict__ in16, const unsigned char* __restrict__ wprep,
               const float* __restrict__ b1, const float* __restrict__ b2,
               unsigned short* __restrict__ out16, const void* __restrict__ batch,
               float* __restrict__ pool, int n, int ntiles, int relu_out)
{
    extern __shared__ char smc[];
    const uint32_t sb = smem_u32(smc);

    const int tid = threadIdx.x;
    const int wid = tid >> 5;
    const int lane = tid & 31;
    const int rg = wid >> 1;          // warp row group (0..3): rows rg*32..+31
    const int cg = wid & 1;           // warp col group (0..1): cols cg*64..+63
    const int is64 = relu_out ? 0 : g_is64;

    // ---- copy prepped weights ONCE per CTA ----
    {
        const uint4* wsrc = (const uint4*)wprep;
        uint4* wdst = (uint4*)(smc + SM_W);
        #pragma unroll 8
        for (int i = tid; i < WL_BYTES / 16; i += 256) wdst[i] = wsrc[i];
    }
    if (tid < DD) {
        ((float*)(smc + SM_B1))[tid] = b1[tid];
        ((float*)(smc + SM_B2))[tid] = b2[tid];
    }

    // per-lane ldmatrix offsets
    const uint32_t a_off = (uint32_t)(rg * 32 + (lane & 15)) * SAB + ((lane >> 4) << 3) * 2;
    const uint32_t ah0 = sb + SM_AH + a_off;
    const int g = lane >> 3, ii = lane & 7;
    const uint32_t b_off = (uint32_t)(cg * 64 + ((g >> 1) << 3) + ii) * SAB + ((g & 1) << 3) * 2;

    #pragma unroll 1
    for (int tile = blockIdx.x; tile < ntiles; tile += gridDim.x) {
        const int row0 = tile * BM;
        if (tile != (int)blockIdx.x) __syncthreads();   // prior tile's ldsm reads done

        // ---- load A tile (bf16 agg, straight copy) ----
        {
            int r = tid >> 1;
            int c0 = (tid & 1) * 64;
            bool valid = (row0 + r) < n;
            const unsigned short* src = in16 + (size_t)(row0 + r) * DD + c0;
            char* ah = smc + SM_AH + r * SAB + c0 * 2;
            #pragma unroll
            for (int c = 0; c < 64; c += 8) {
                uint4 v = valid ? *(const uint4*)(src + c) : make_uint4(0u, 0u, 0u, 0u);
                *(uint4*)(ah + c * 2) = v;
            }
        }
        __syncthreads();   // A visible (first iter: also weights/biases)

        float acc[2][8][4];

        // ======== stage 1: D1 = A @ W1 ========
        #pragma unroll
        for (int mt = 0; mt < 2; ++mt)
            #pragma unroll
            for (int nt = 0; nt < 8; ++nt)
                #pragma unroll
                for (int q = 0; q < 4; ++q) acc[mt][nt][q] = 0.f;

        gemm_stage(ah0, sb + SM_W + b_off, sb + SM_W + MATB + b_off, acc);
        __syncthreads();   // all A reads done before overwrite

        // epilogue 1: z = relu(D1 + b1) -> bf16 back into A
        {
            const float* sb1 = (const float*)(smc + SM_B1);
            const int qr = lane >> 2;
            const int qc = (lane & 3) * 2;
            #pragma unroll
            for (int mt = 0; mt < 2; ++mt) {
                #pragma unroll
                for (int nt = 0; nt < 8; ++nt) {
                    int row = rg * 32 + mt * 16 + qr;
                    int col = cg * 64 + nt * 8 + qc;
                    float bj0 = sb1[col], bj1 = sb1[col + 1];
                    float z0 = fmaxf(acc[mt][nt][0] + bj0, 0.f);
                    float z1 = fmaxf(acc[mt][nt][1] + bj1, 0.f);
                    float z2 = fmaxf(acc[mt][nt][2] + bj0, 0.f);
                    float z3 = fmaxf(acc[mt][nt][3] + bj1, 0.f);
                    uint32_t o0 = (uint32_t)row * SAB + (uint32_t)col * 2;
                    uint32_t o1 = (uint32_t)(row + 8) * SAB + (uint32_t)col * 2;
                    *(uint32_t*)(smc + SM_AH + o0) = (uint32_t)f2bf(z0) | ((uint32_t)f2bf(z1) << 16);
                    *(uint32_t*)(smc + SM_AH + o1) = (uint32_t)f2bf(z2) | ((uint32_t)f2bf(z3) << 16);
                }
            }
        }
        __syncthreads();

        // ======== stage 2: D2 = Z @ W2 ========
        #pragma unroll
        for (int mt = 0; mt < 2; ++mt)
            #pragma unroll
            for (int nt = 0; nt < 8; ++nt)
                #pragma unroll
                for (int q = 0; q < 4; ++q) acc[mt][nt][q] = 0.f;

        gemm_stage(ah0, sb + SM_W + 2 * MATB + b_off, sb + SM_W + 3 * MATB + b_off, acc);

        // epilogue 2
        {
            const float* sb2 = (const float*)(smc + SM_B2);
            const int qr = lane >> 2;
            const int qc = (lane & 3) * 2;
            #pragma unroll
            for (int mt = 0; mt < 2; ++mt) {
                int row = rg * 32 + mt * 16 + qr;
                int grow0 = row0 + row;
                int grow1 = grow0 + 8;
                if (relu_out) {
                    #pragma unroll
                    for (int nt = 0; nt < 8; ++nt) {
                        int col = cg * 64 + nt * 8 + qc;
                        float bj0 = sb2[col], bj1 = sb2[col + 1];
                        float o0 = fmaxf(acc[mt][nt][0] + bj0, 0.f);
                        float o1 = fmaxf(acc[mt][nt][1] + bj1, 0.f);
                        float o2 = fmaxf(acc[mt][nt][2] + bj0, 0.f);
                        float o3 = fmaxf(acc[mt][nt][3] + bj1, 0.f);
                        if (grow0 < n)
                            *(uint32_t*)(out16 + (size_t)grow0 * DD + col) =
                                (uint32_t)f2bf(o0) | ((uint32_t)f2bf(o1) << 16);
                        if (grow1 < n)
                            *(uint32_t*)(out16 + (size_t)grow1 * DD + col) =
                                (uint32_t)f2bf(o2) | ((uint32_t)f2bf(o3) << 16);
                    }
                } else {
                    // last layer: accumulate straight into pool[batch[row]] (fp32, exact path)
                    int g0 = (grow0 < n) ? load_idx(batch, grow0, is64) : -1;
                    int g1 = (grow1 < n) ? load_idx(batch, grow1, is64) : -1;
                    bool v0 = (unsigned)g0 < (unsigned)NGRAPH;
                    bool v1 = (unsigned)g1 < (unsigned)NGRAPH;
                    #pragma unroll
                    for (int nt = 0; nt < 8; ++nt) {
                        int col = cg * 64 + nt * 8 + qc;
                        float bj0 = sb2[col], bj1 = sb2[col + 1];
                        if (v0) red_add_v2(pool + g0 * DD + col,
                                           acc[mt][nt][0] + bj0, acc[mt][nt][1] + bj1);
                        if (v1) red_add_v2(pool + g1 * DD + col,
                                           acc[mt][nt][2] + bj0, acc[mt][nt][3] + bj1);
                    }
                }
            }
        }
    }
}

// ---------- finalize: pooled mean + logits ----------
__global__ void finalize_kernel(const float* __restrict__ pool, const float* __restrict__ cnt,
                                const float* __restrict__ wlin, const float* __restrict__ blin,
                                float* __restrict__ out_pooled, float* __restrict__ out_logits) {
    __shared__ float ps[DD];
    int g = blockIdx.x;
    int t = threadIdx.x;
    float c = fmaxf(cnt[g], 1.0f);
    float v = pool[g * DD + t] / c;
    ps[t] = v;
    out_pooled[g * DD + t] = v;
    __syncthreads();
    if (t < NCLASS) {
        float s = blin[t];
        #pragma unroll 4
        for (int k = 0; k < DD; ++k) s += ps[k] * wlin[k * NCLASS + t];
        out_logits[g * NCLASS + t] = s;
    }
}

extern "C" void kernel_launch(void* const* d_in, const int* in_sizes, int n_in,
                              void* d_out, int out_size) {
    const float* x     = (const float*)d_in[0];
    const void*  ei    = d_in[1];
    const void*  batch = d_in[2];
    const float* w1    = (const float*)d_in[3];
    const float* b1    = (const float*)d_in[4];
    const float* w2    = (const float*)d_in[5];
    const float* b2    = (const float*)d_in[6];
    const float* wlin  = (const float*)d_in[7];
    const float* blin  = (const float*)d_in[8];
    float* out = (float*)d_out;

    int n  = in_sizes[0] / DD;
    int ne = in_sizes[1] / 2;
    if (n > NODES_MAX) n = NODES_MAX;
    if (ne > NE_MAX) ne = NE_MAX;

    float *pPool, *pCnt, *pScratch;
    unsigned short *pX16, *pH16, *pAgg16;
    int *pDeg, *pOff, *pCur, *pEsrc, *pBlk;
    unsigned char* pW;
    cudaGetSymbolAddress((void**)&pX16, g_x16);
    cudaGetSymbolAddress((void**)&pAgg16, g_agg16);
    cudaGetSymbolAddress((void**)&pH16, g_h16);
    cudaGetSymbolAddress((void**)&pPool, g_pool);
    cudaGetSymbolAddress((void**)&pCnt, g_cnt);
    cudaGetSymbolAddress((void**)&pScratch, g_scratch);
    cudaGetSymbolAddress((void**)&pDeg, g_deg);
    cudaGetSymbolAddress((void**)&pOff, g_off);
    cudaGetSymbolAddress((void**)&pCur, g_cur);
    cudaGetSymbolAddress((void**)&pEsrc, g_esrc);
    cudaGetSymbolAddress((void**)&pBlk, g_blk);
    cudaGetSymbolAddress((void**)&pW, g_wprep);

    cudaFuncSetAttribute(mlp_mma_kernel, cudaFuncAttributeMaxDynamicSharedMemorySize, MLP_SMEM);

    const int ntiles     = (n + BM - 1) / BM;
    const int hwarp_grid = (n * 16 + 255) / 256;
    const int edge_grid  = (ne + 255) / 256;
    const int nb         = (n + 255) / 256;

    detect_kernel<<<1, 32>>>((const int*)ei);
    wprep_kernel<<<512, 256>>>(w1, w2, n);   // also zeroes deg/pool/cnt
    xconv_kernel<<<(n * 32 + 255) / 256, 256>>>(x, pX16, n * 32);

    // ---- CSR build (fast 3-kernel scan) ----
    hist_kernel<<<edge_grid, 256>>>(ei, pDeg, ne, n);
    blockscan_kernel<<<nb, 256>>>(pDeg, pOff, pBlk, n);
    scan2_kernel<<<1, 256>>>(pBlk, pOff, n, nb);
    addoff_kernel<<<nb, 256>>>(pOff, pCur, pBlk, batch, pCnt, n);
    fill_kernel<<<edge_grid, 256>>>(ei, pCur, pEsrc, ne, n);

    // per layer: gather (bf16) -> bf16 agg -> persistent MLP
    for (int L = 0; L < 4; ++L) {
        const unsigned short* hsrc = (L == 0) ? pX16 : pH16;
        gather_bf16_kernel<<<hwarp_grid, 256>>>(hsrc, pOff, pEsrc, pAgg16, n);
        mlp_mma_kernel<<<MLP_GRID, 256, MLP_SMEM>>>(
            pAgg16, pW + (size_t)L * WL_BYTES, b1 + (size_t)L * DD, b2 + (size_t)L * DD,
            pH16, batch, pPool, n, ntiles, (L < 3) ? 1 : 0);
    }

    float* out_pooled = pScratch;
    float* out_logits = pScratch + NGRAPH * DD;
    if (out_size >= NGRAPH * DD + NGRAPH * NCLASS) {
        out_pooled = out;
        out_logits = out + NGRAPH * DD;
    } else if (out_size == NGRAPH * NCLASS) {
        out_logits = out;
    } else if (out_size == NGRAPH * DD) {
        out_pooled = out;
    }
    finalize_kernel<<<NGRAPH, DD>>>(pPool, pCnt, wlin, blin, out_pooled, out_logits);
}